// round 8
// baseline (speedup 1.0000x reference)
#include <cuda_runtime.h>
#include <cuda_fp16.h>
#include <cstdint>
#include <math.h>

#define N_NODES 50000
#define N_EDGES 800000
#define HID 128
#define EC 100
#define IN_DIM 5
#define N_BLOCKS 6
#define NT 512
#define NTILES 6250

// ---------------- scratch (device globals; no runtime allocation) ----------------
__device__ float g_x[N_NODES * HID];
__device__ float g_agg[N_NODES * HID];
__device__ float g_C[N_EDGES];
__device__ uint32_t g_eaf[(size_t)NTILES * 8192];   // eattr, fragment-order fp16 (204.8 MB)

__device__ __forceinline__ float sspf(float x) {
    float sp = fmaxf(x, 0.0f) + log1pf(expf(-fabsf(x)));
    return sp - 0.69314718055994531f;
}

// pack two f32 into f16x2 (lo = first arg)
__device__ __forceinline__ uint32_t h2(float lo, float hi) {
    uint32_t r;
    asm("cvt.rn.f16x2.f32 %0, %1, %2;" : "=r"(r) : "f"(hi), "f"(lo));
    return r;
}

// ---------------- fp16 fragment-order smem layout (strides in 32-bit words) -------
// chunk = 32 k = 2 ksteps of m16n8k16.
// A-frag: [i-tile 0..7][ks 0..1][lane 0..31][w 0..3]  w = {a0,a1,a2,a3}
// B-frag: [pair 0..7][ks 0..1][lane 0..31][w 0..3]    w = {j0b0,j0b1,j1b0,j1b1}
// T-frag: [i-tile 0..7][ks 0..7][lane][w]             (resident 128x128 half tile)
#define KS_STR 132
#define AI_STR 264
#define AWORDS 2112
#define BP_STR 264
#define BWORDS 2112
#define TI_STR 1056
#define TWORDS 8448

#define EDGE_SMEM ((TWORDS + 2 * BWORDS) * 4)
#define NODE_SMEM ((TWORDS + 2 * AWORDS + 2 * BWORDS) * 4)
#define PLAIN_SMEM ((2 * AWORDS + 2 * BWORDS) * 4)

// ---------------- global->reg loaders (512 threads: 2 float4 each) ----------------
__device__ __forceinline__ void loadA_g(float4* r, const float* __restrict__ A,
                                        int mBase, int k0, int M, int K, int tid) {
#pragma unroll
    for (int i = 0; i < 2; i++) {
        int q = tid + (i << 9);
        int row = q >> 3, kq = (q & 7) << 2;
        int gm = mBase + row, gk = k0 + kq;
        r[i] = make_float4(0.f, 0.f, 0.f, 0.f);
        if (gm < M && gk < K)
            r[i] = *reinterpret_cast<const float4*>(A + (size_t)gm * K + gk);
    }
}
__device__ __forceinline__ void loadB_g(float4* r, const float* __restrict__ B,
                                        int k0, int K, int tid) {
#pragma unroll
    for (int i = 0; i < 2; i++) {
        int q = tid + (i << 9);
        int kr = q >> 5, nq = (q & 31) << 2;
        int gk = k0 + kr;
        r[i] = make_float4(0.f, 0.f, 0.f, 0.f);
        if (gk < K)
            r[i] = *reinterpret_cast<const float4*>(B + (size_t)gk * 128 + nq);
    }
}

// ---------------- reg->smem fp16 fragment-order stores ----------------
__device__ __forceinline__ void storeA_f(uint32_t* __restrict__ buf, const float4* r, int tid) {
#pragma unroll
    for (int i4 = 0; i4 < 2; i4++) {
        int q = tid + (i4 << 9);
        int row = q >> 3, kq = (q & 7) << 2;
        int iT = row >> 4, rl = row & 15;
        int g = rl & 7, hr = rl >> 3;
        int ks = kq >> 4, kl = kq & 15;
        int w = hr + ((kl & 8) ? 2 : 0);
        int t0 = (kl & 7) >> 1;
        uint32_t* p = buf + iT * AI_STR + ks * KS_STR + (g * 4 + t0) * 4 + w;
        p[0] = h2(r[i4].x, r[i4].y);
        p[4] = h2(r[i4].z, r[i4].w);
    }
}
__device__ __forceinline__ void storeB_f(uint32_t* __restrict__ buf, const float4* r, int tid) {
    __half* hb = reinterpret_cast<__half*>(buf);
#pragma unroll
    for (int i4 = 0; i4 < 2; i4++) {
        int q = tid + (i4 << 9);
        int kr = q >> 5, nq = (q & 31) << 2;
        int ks = kr >> 4, krl = kr & 15;
        int t = (krl & 7) >> 1;
        int hl = krl & 1;
        int wb = (krl >> 3) & 1;
        const float vv[4] = { r[i4].x, r[i4].y, r[i4].z, r[i4].w };
#pragma unroll
        for (int d = 0; d < 4; d++) {
            int n = nq + d;
            int pairI = n >> 4, jpar = (n >> 3) & 1, g0 = n & 7;
            int w = jpar * 2 + wb;
            int word = pairI * BP_STR + ks * KS_STR + (g0 * 4 + t) * 4 + w;
            hb[word * 2 + hl] = __float2half_rn(vv[d]);
        }
    }
}

// ---------------- mma: one 32-k chunk, smem A ----------------
template<int ISTR>
__device__ __forceinline__ void mma_chunk_f(const uint32_t* __restrict__ As,
                                            const uint32_t* __restrict__ Bs,
                                            float c[2][4][4], int wid, int lane)
{
    const uint32_t* Ab = As + ((wid & 3) * 2) * ISTR + lane * 4;
    const uint32_t* Bb = Bs + ((wid >> 2) * 2) * BP_STR + lane * 4;
#pragma unroll
    for (int ks = 0; ks < 2; ks++) {
        uint4 av[2], bv[2];
#pragma unroll
        for (int i = 0; i < 2; i++)
            av[i] = *reinterpret_cast<const uint4*>(Ab + i * ISTR + ks * KS_STR);
#pragma unroll
        for (int p = 0; p < 2; p++)
            bv[p] = *reinterpret_cast<const uint4*>(Bb + p * BP_STR + ks * KS_STR);
#pragma unroll
        for (int i = 0; i < 2; i++)
#pragma unroll
            for (int j = 0; j < 4; j++) {
                uint32_t b0 = (j & 1) ? bv[j >> 1].z : bv[j >> 1].x;
                uint32_t b1 = (j & 1) ? bv[j >> 1].w : bv[j >> 1].y;
                asm volatile(
                    "mma.sync.aligned.m16n8k16.row.col.f32.f16.f16.f32 "
                    "{%0,%1,%2,%3}, {%4,%5,%6,%7}, {%8,%9}, {%0,%1,%2,%3};\n"
                    : "+f"(c[i][j][0]), "+f"(c[i][j][1]), "+f"(c[i][j][2]), "+f"(c[i][j][3])
                    : "r"(av[i].x), "r"(av[i].y), "r"(av[i].z), "r"(av[i].w),
                      "r"(b0), "r"(b1));
            }
    }
}

// ---------------- mma: one 32-k chunk, A fragments in registers ----------------
__device__ __forceinline__ void mma_chunk_ra(const uint4* aC,   // [ks*2+i]
                                             const uint32_t* __restrict__ Bs,
                                             float c[2][4][4], int wid, int lane)
{
    const uint32_t* Bb = Bs + ((wid >> 2) * 2) * BP_STR + lane * 4;
#pragma unroll
    for (int ks = 0; ks < 2; ks++) {
        uint4 bv[2];
#pragma unroll
        for (int p = 0; p < 2; p++)
            bv[p] = *reinterpret_cast<const uint4*>(Bb + p * BP_STR + ks * KS_STR);
#pragma unroll
        for (int i = 0; i < 2; i++) {
            const uint4 av = aC[ks * 2 + i];
#pragma unroll
            for (int j = 0; j < 4; j++) {
                uint32_t b0 = (j & 1) ? bv[j >> 1].z : bv[j >> 1].x;
                uint32_t b1 = (j & 1) ? bv[j >> 1].w : bv[j >> 1].y;
                asm volatile(
                    "mma.sync.aligned.m16n8k16.row.col.f32.f16.f16.f32 "
                    "{%0,%1,%2,%3}, {%4,%5,%6,%7}, {%8,%9}, {%0,%1,%2,%3};\n"
                    : "+f"(c[i][j][0]), "+f"(c[i][j][1]), "+f"(c[i][j][2]), "+f"(c[i][j][3])
                    : "r"(av.x), "r"(av.y), "r"(av.z), "r"(av.w),
                      "r"(b0), "r"(b1));
            }
        }
    }
}

__device__ __forceinline__ void zero_c(float c[2][4][4]) {
#pragma unroll
    for (int i = 0; i < 2; i++)
#pragma unroll
        for (int j = 0; j < 4; j++)
#pragma unroll
            for (int v = 0; v < 4; v++) c[i][j][v] = 0.0f;
}

// store epilogue values (optionally ssp) into T fragment layout (half2 words)
__device__ __forceinline__ void store_T_frag(uint32_t* __restrict__ Tt, const float c[2][4][4],
                                             const float* bn, int wid, int g, int t,
                                             int warpN, bool doSsp)
{
    const int iTb = (wid & 3) * 2;
    const int ksBase = warpN >> 4;
#pragma unroll
    for (int i = 0; i < 2; i++)
#pragma unroll
        for (int half = 0; half < 2; half++)
#pragma unroll
            for (int j = 0; j < 4; j++) {
                float v0 = c[i][j][half * 2 + 0] + bn[j * 2 + 0];
                float v1 = c[i][j][half * 2 + 1] + bn[j * 2 + 1];
                if (doSsp) { v0 = sspf(v0); v1 = sspf(v1); }
                int ks = ksBase + (j >> 1);
                int w = half + 2 * (j & 1);
                Tt[(iTb + i) * TI_STR + ks * KS_STR + (g * 4 + t) * 4 + w] = h2(v0, v1);
            }
}

// ---------------- eattr pre-pack: f32 row-major -> fragment-order fp16 ------------
__global__ void pack_eattr(const float* __restrict__ ea, uint32_t* __restrict__ out) {
    size_t idx = (size_t)blockIdx.x * 256 + threadIdx.x;
    if (idx >= (size_t)NTILES * 8192) return;
    int tile = (int)(idx >> 13);
    int rem  = (int)(idx & 8191);
    int iT = rem >> 10;
    int ks = (rem >> 7) & 7;
    int lane = (rem >> 2) & 31;
    int w = rem & 3;
    int g = lane >> 2, t = lane & 3;
    int row = iT * 16 + (w & 1) * 8 + g;
    int k = ks * 16 + t * 2 + ((w & 2) ? 8 : 0);
    size_t e = (size_t)tile * 128 + row;
    float v0 = 0.f, v1 = 0.f;
    if (k < EC)     v0 = ea[e * EC + k];
    if (k + 1 < EC) v1 = ea[e * EC + k + 1];
    out[idx] = h2(v0, v1);
}

// ---------------- fused edge kernel: GEMM+ssp+GEMM+mask + v4-scatter --------------
__global__ void __launch_bounds__(NT, 1) edge_fused(
    const uint32_t* __restrict__ eaf, const float* __restrict__ B1, const float* __restrict__ b1,
    const float* __restrict__ B2, const float* __restrict__ b2,
    const float* __restrict__ Cm, const int* __restrict__ src, const int* __restrict__ dst,
    const float* __restrict__ x, float* __restrict__ agg)
{
    extern __shared__ uint32_t sm[];
    uint32_t* Tt  = sm;
    uint32_t* Bs0 = sm + TWORDS;
    uint32_t* Bs1 = Bs0 + BWORDS;

    const int tid = threadIdx.x;
    const int wid = tid >> 5, lane = tid & 31;
    const int g = lane >> 2, t = lane & 3;
    const int warpM = (wid & 3) * 32, warpN = (wid >> 2) * 32;
    const int mBase = blockIdx.x * 128;

    float c[2][4][4];
    zero_c(c);
    float4 bR[2];

    // per-warp A fragment base in gmem (fragment-order, coalesced LDG.128)
    const uint32_t* Af = eaf + (size_t)blockIdx.x * 8192 + ((wid & 3) * 2) * 1024 + lane * 4;

    uint4 aC[4], aN[4];
#pragma unroll
    for (int s = 0; s < 2; s++)
#pragma unroll
        for (int i = 0; i < 2; i++)
            aC[s * 2 + i] = *reinterpret_cast<const uint4*>(Af + i * 1024 + s * 128);

    loadB_g(bR, B1, 0, EC, tid);
    storeB_f(Bs0, bR, tid);
    __syncthreads();
    for (int ch = 0; ch < 4; ch++) {
        if (ch < 3) {
#pragma unroll
            for (int s = 0; s < 2; s++)
#pragma unroll
                for (int i = 0; i < 2; i++)
                    aN[s * 2 + i] = *reinterpret_cast<const uint4*>(
                        Af + i * 1024 + ((ch + 1) * 2 + s) * 128);
            loadB_g(bR, B1, (ch + 1) * 32, EC, tid);
        }
        mma_chunk_ra(aC, (ch & 1) ? Bs1 : Bs0, c, wid, lane);
        if (ch < 3) {
            storeB_f(((ch + 1) & 1) ? Bs1 : Bs0, bR, tid);
#pragma unroll
            for (int q = 0; q < 4; q++) aC[q] = aN[q];
        }
        __syncthreads();
    }

    float bn1[8];
#pragma unroll
    for (int j = 0; j < 4; j++) {
        bn1[j * 2 + 0] = __ldg(b1 + warpN + j * 8 + t * 2 + 0);
        bn1[j * 2 + 1] = __ldg(b1 + warpN + j * 8 + t * 2 + 1);
    }
    store_T_frag(Tt, c, bn1, wid, g, t, warpN, true);
    zero_c(c);

    // stage 2: T (resident) @ B2
    loadB_g(bR, B2, 0, 128, tid);
    __syncthreads();
    storeB_f(Bs0, bR, tid);
    __syncthreads();
    for (int ch = 0; ch < 4; ch++) {
        if (ch < 3) loadB_g(bR, B2, (ch + 1) * 32, 128, tid);
        mma_chunk_f<TI_STR>(Tt + ch * 2 * KS_STR, (ch & 1) ? Bs1 : Bs0, c, wid, lane);
        if (ch < 3) storeB_f(((ch + 1) & 1) ? Bs1 : Bs0, bR, tid);
        __syncthreads();
    }

    // scatter epilogue: lane-pair shuffle -> red.global.add.v4.f32
    float bn2[8];
#pragma unroll
    for (int j = 0; j < 4; j++) {
        bn2[j * 2 + 0] = __ldg(b2 + warpN + j * 8 + t * 2 + 0);
        bn2[j * 2 + 1] = __ldg(b2 + warpN + j * 8 + t * 2 + 1);
    }
#pragma unroll
    for (int i = 0; i < 2; i++)
#pragma unroll
        for (int half = 0; half < 2; half++) {
            const int e = mBase + warpM + i * 16 + g + half * 8;
            const float cmv = __ldg(Cm + e);
            const int s = __ldg(src + e), d = __ldg(dst + e);
            const float* xr = x + (size_t)s * 128;
            float* ar = agg + (size_t)d * 128;
            const bool active = (cmv != 0.0f) && ((t & 1) == 0);
#pragma unroll
            for (int j = 0; j < 4; j++) {
                float w0 = (c[i][j][half * 2 + 0] + bn2[j * 2 + 0]) * cmv;
                float w1 = (c[i][j][half * 2 + 1] + bn2[j * 2 + 1]) * cmv;
                double pk = __hiloint2double(__float_as_int(w1), __float_as_int(w0));
                double other = __shfl_xor_sync(0xffffffffu, pk, 1);
                if (active) {
                    float o0 = __int_as_float(__double2loint(other));
                    float o1 = __int_as_float(__double2hiint(other));
                    const int col = warpN + j * 8 + t * 2;
                    float4 xv = *reinterpret_cast<const float4*>(xr + col);
                    float m0 = xv.x * w0, m1 = xv.y * w1;
                    float m2 = xv.z * o0, m3 = xv.w * o1;
                    asm volatile("red.global.add.v4.f32 [%0], {%1, %2, %3, %4};"
                                 :: "l"(ar + col), "f"(m0), "f"(m1), "f"(m2), "f"(m3)
                                 : "memory");
                }
            }
        }
}

// ---------------- fused node kernel ----------------
__global__ void __launch_bounds__(NT, 1) node_fused(
    const float* __restrict__ agg, const float* __restrict__ B1, const float* __restrict__ b1,
    const float* __restrict__ B2, const float* __restrict__ b2,
    float* __restrict__ h, const float* __restrict__ lin1, float* __restrict__ xOut)
{
    extern __shared__ uint32_t sm[];
    uint32_t* Tt  = sm;
    uint32_t* As0 = sm + TWORDS;
    uint32_t* As1 = As0 + AWORDS;
    uint32_t* Bs0 = As1 + AWORDS;
    uint32_t* Bs1 = Bs0 + BWORDS;

    const int tid = threadIdx.x;
    const int wid = tid >> 5, lane = tid & 31;
    const int g = lane >> 2, t = lane & 3;
    const int warpM = (wid & 3) * 32, warpN = (wid >> 2) * 32;
    const int mBase = blockIdx.x * 128;

    float c[2][4][4];
    zero_c(c);
    float4 aR[2], bR[2];

    // stage 1: agg @ B1 (K=128)
    loadA_g(aR, agg, mBase, 0, N_NODES, 128, tid);
    loadB_g(bR, B1, 0, 128, tid);
    storeA_f(As0, aR, tid);
    storeB_f(Bs0, bR, tid);
    __syncthreads();
    for (int ch = 0; ch < 4; ch++) {
        if (ch < 3) {
            loadA_g(aR, agg, mBase, (ch + 1) * 32, N_NODES, 128, tid);
            loadB_g(bR, B1, (ch + 1) * 32, 128, tid);
        }
        mma_chunk_f<AI_STR>((ch & 1) ? As1 : As0, (ch & 1) ? Bs1 : Bs0, c, wid, lane);
        if (ch < 3) {
            storeA_f(((ch + 1) & 1) ? As1 : As0, aR, tid);
            storeB_f(((ch + 1) & 1) ? Bs1 : Bs0, bR, tid);
        }
        __syncthreads();
    }

    float bn1[8];
#pragma unroll
    for (int j = 0; j < 4; j++) {
        bn1[j * 2 + 0] = __ldg(b1 + warpN + j * 8 + t * 2 + 0);
        bn1[j * 2 + 1] = __ldg(b1 + warpN + j * 8 + t * 2 + 1);
    }
    store_T_frag(Tt, c, bn1, wid, g, t, warpN, true);
    zero_c(c);

    // stage 2: T @ B2
    loadB_g(bR, B2, 0, 128, tid);
    __syncthreads();
    storeB_f(Bs0, bR, tid);
    __syncthreads();
    for (int ch = 0; ch < 4; ch++) {
        if (ch < 3) loadB_g(bR, B2, (ch + 1) * 32, 128, tid);
        mma_chunk_f<TI_STR>(Tt + ch * 2 * KS_STR, (ch & 1) ? Bs1 : Bs0, c, wid, lane);
        if (ch < 3) storeB_f(((ch + 1) & 1) ? Bs1 : Bs0, bR, tid);
        __syncthreads();
    }

    // stage-2 epilogue: h += residual; keep hnew resident in T-frag
    float bn2[8];
#pragma unroll
    for (int j = 0; j < 4; j++) {
        bn2[j * 2 + 0] = __ldg(b2 + warpN + j * 8 + t * 2 + 0);
        bn2[j * 2 + 1] = __ldg(b2 + warpN + j * 8 + t * 2 + 1);
    }
    const int iTb = (wid & 3) * 2;
    const int ksBase = warpN >> 4;
#pragma unroll
    for (int i = 0; i < 2; i++)
#pragma unroll
        for (int half = 0; half < 2; half++) {
            const int gm = mBase + warpM + i * 16 + g + half * 8;
            const bool ok = gm < N_NODES;
            float* hrow = h + (size_t)gm * 128;
#pragma unroll
            for (int j = 0; j < 4; j++) {
                const int col = warpN + j * 8 + t * 2;
                float v0 = c[i][j][half * 2 + 0] + bn2[j * 2 + 0];
                float v1 = c[i][j][half * 2 + 1] + bn2[j * 2 + 1];
                if (ok) {
                    float2 hv = *reinterpret_cast<const float2*>(hrow + col);
                    v0 += hv.x; v1 += hv.y;
                    *reinterpret_cast<float2*>(hrow + col) = make_float2(v0, v1);
                }
                int ks = ksBase + (j >> 1);
                int w = half + 2 * (j & 1);
                Tt[(iTb + i) * TI_STR + ks * KS_STR + (g * 4 + t) * 4 + w] = h2(v0, v1);
            }
        }

    // stage 3: xOut = hnew @ lin1 (next block's lin1)
    if (lin1 != nullptr) {
        zero_c(c);
        loadB_g(bR, lin1, 0, 128, tid);
        __syncthreads();
        storeB_f(Bs0, bR, tid);
        __syncthreads();
        for (int ch = 0; ch < 4; ch++) {
            if (ch < 3) loadB_g(bR, lin1, (ch + 1) * 32, 128, tid);
            mma_chunk_f<TI_STR>(Tt + ch * 2 * KS_STR, (ch & 1) ? Bs1 : Bs0, c, wid, lane);
            if (ch < 3) storeB_f(((ch + 1) & 1) ? Bs1 : Bs0, bR, tid);
            __syncthreads();
        }
#pragma unroll
        for (int i = 0; i < 2; i++)
#pragma unroll
            for (int half = 0; half < 2; half++) {
                const int gm = mBase + warpM + i * 16 + g + half * 8;
                if (gm < N_NODES) {
                    float* orow = xOut + (size_t)gm * 128;
#pragma unroll
                    for (int j = 0; j < 4; j++) {
                        const int col = warpN + j * 8 + t * 2;
                        *reinterpret_cast<float2*>(orow + col) =
                            make_float2(c[i][j][half * 2 + 0], c[i][j][half * 2 + 1]);
                    }
                }
            }
    }
}

// ---------------- plain GEMM (initial x = h @ lin1_0) ----------------
__global__ void __launch_bounds__(NT, 1) gemm_plain(
    const float* __restrict__ A, const float* __restrict__ B,
    float* __restrict__ out, int M)
{
    extern __shared__ uint32_t sm[];
    uint32_t* As0 = sm;
    uint32_t* As1 = As0 + AWORDS;
    uint32_t* Bs0 = As1 + AWORDS;
    uint32_t* Bs1 = Bs0 + BWORDS;

    const int tid = threadIdx.x;
    const int wid = tid >> 5, lane = tid & 31;
    const int g = lane >> 2, t = lane & 3;
    const int warpM = (wid & 3) * 32, warpN = (wid >> 2) * 32;
    const int mBase = blockIdx.x * 128;

    float c[2][4][4];
    zero_c(c);
    float4 aR[2], bR[2];
    loadA_g(aR, A, mBase, 0, M, 128, tid);
    loadB_g(bR, B, 0, 128, tid);
    storeA_f(As0, aR, tid);
    storeB_f(Bs0, bR, tid);
    __syncthreads();
    for (int ch = 0; ch < 4; ch++) {
        if (ch < 3) {
            loadA_g(aR, A, mBase, (ch + 1) * 32, M, 128, tid);
            loadB_g(bR, B, (ch + 1) * 32, 128, tid);
        }
        mma_chunk_f<AI_STR>((ch & 1) ? As1 : As0, (ch & 1) ? Bs1 : Bs0, c, wid, lane);
        if (ch < 3) {
            storeA_f(((ch + 1) & 1) ? As1 : As0, aR, tid);
            storeB_f(((ch + 1) & 1) ? Bs1 : Bs0, bR, tid);
        }
        __syncthreads();
    }
#pragma unroll
    for (int i = 0; i < 2; i++)
#pragma unroll
        for (int half = 0; half < 2; half++) {
            const int gm = mBase + warpM + i * 16 + g + half * 8;
            if (gm < M) {
                float* orow = out + (size_t)gm * 128;
#pragma unroll
                for (int j = 0; j < 4; j++) {
                    const int col = warpN + j * 8 + t * 2;
                    *reinterpret_cast<float2*>(orow + col) =
                        make_float2(c[i][j][half * 2 + 0], c[i][j][half * 2 + 1]);
                }
            }
        }
}

// ---------------- small kernels ----------------
__global__ void embed_kernel(const float* __restrict__ z, const float* __restrict__ w,
                             const float* __restrict__ b, float* __restrict__ h) {
    int n = blockIdx.x, j = threadIdx.x;
    const float* zr = z + (size_t)n * (IN_DIM + HID);
    float acc = b[j] + zr[IN_DIM + j];
#pragma unroll
    for (int k = 0; k < IN_DIM; k++) acc = fmaf(zr[k], w[k * HID + j], acc);
    h[(size_t)n * HID + j] = acc;
}

__global__ void cmask_kernel(const float* __restrict__ len, float* __restrict__ C) {
    int e = blockIdx.x * 256 + threadIdx.x;
    if (e < N_EDGES) {
        float l = len[e];
        C[e] = (l <= 10.0f && l >= 0.0f) ? 1.0f : 0.0f;
    }
}

__global__ void zero_kernel(float4* __restrict__ p, int n4) {
    int i = blockIdx.x * 256 + threadIdx.x;
    if (i < n4) p[i] = make_float4(0.f, 0.f, 0.f, 0.f);
}

// ---------------- host launch ----------------
extern "C" void kernel_launch(void* const* d_in, const int* in_sizes, int n_in,
                              void* d_out, int out_size) {
    const float* z      = (const float*)d_in[0];
    const int*   ei     = (const int*)  d_in[1];
    const float* elen   = (const float*)d_in[2];
    const float* eattr  = (const float*)d_in[3];
    const float* emb_w  = (const float*)d_in[4];
    const float* emb_b  = (const float*)d_in[5];
    const float* lin1_w = (const float*)d_in[6];
    const float* nn_w1  = (const float*)d_in[7];
    const float* nn_b1  = (const float*)d_in[8];
    const float* nn_w2  = (const float*)d_in[9];
    const float* nn_b2  = (const float*)d_in[10];
    const float* lin2_w = (const float*)d_in[11];
    const float* lin2_b = (const float*)d_in[12];
    const float* lin_w  = (const float*)d_in[13];
    const float* lin_b  = (const float*)d_in[14];
    float* h = (float*)d_out;

    float *px, *pagg, *pC;
    uint32_t* peaf;
    cudaGetSymbolAddress((void**)&px,   g_x);
    cudaGetSymbolAddress((void**)&pagg, g_agg);
    cudaGetSymbolAddress((void**)&pC,   g_C);
    cudaGetSymbolAddress((void**)&peaf, g_eaf);

    cudaFuncSetAttribute(edge_fused, cudaFuncAttributeMaxDynamicSharedMemorySize, EDGE_SMEM);
    cudaFuncSetAttribute(node_fused, cudaFuncAttributeMaxDynamicSharedMemorySize, NODE_SMEM);
    cudaFuncSetAttribute(gemm_plain, cudaFuncAttributeMaxDynamicSharedMemorySize, PLAIN_SMEM);

    const int* src = ei;
    const int* dst = ei + N_EDGES;

    embed_kernel<<<N_NODES, HID>>>(z, emb_w, emb_b, h);
    cmask_kernel<<<(N_EDGES + 255) / 256, 256>>>(elen, pC);
    {
        size_t words = (size_t)NTILES * 8192;
        pack_eattr<<<(unsigned)((words + 255) / 256), 256>>>(eattr, peaf);
    }

    const int nodeTiles = (N_NODES + 127) / 128;   // 391
    const int aggN4 = N_NODES * HID / 4;

    gemm_plain<<<nodeTiles, NT, PLAIN_SMEM>>>(h, lin1_w, px, N_NODES);

    for (int i = 0; i < N_BLOCKS; i++) {
        zero_kernel<<<(aggN4 + 255) / 256, 256>>>((float4*)pagg, aggN4);
        edge_fused<<<NTILES, NT, EDGE_SMEM>>>(
            peaf, nn_w1 + (size_t)i * EC * HID, nn_b1 + (size_t)i * HID,
            nn_w2 + (size_t)i * HID * HID, nn_b2 + (size_t)i * HID,
            pC, src, dst, px, pagg);
        const float* lin1next = (i + 1 < N_BLOCKS) ? (lin1_w + (size_t)(i + 1) * HID * HID) : nullptr;
        node_fused<<<nodeTiles, NT, NODE_SMEM>>>(
            pagg, lin2_w + (size_t)i * HID * HID, lin2_b + (size_t)i * HID,
            lin_w + (size_t)i * HID * HID, lin_b + (size_t)i * HID,
            h, lin1next, px);
    }
}

// round 9
// speedup vs baseline: 1.0797x; 1.0797x over previous
#include <cuda_runtime.h>
#include <cuda_fp16.h>
#include <cstdint>
#include <math.h>

#define N_NODES 50000
#define N_EDGES 800000
#define HID 128
#define EC 100
#define IN_DIM 5
#define N_BLOCKS 6
#define NT 512
#define NTILES 6250

// ---------------- scratch (device globals; no runtime allocation) ----------------
__device__ float g_x[N_NODES * HID];
__device__ float g_agg[N_NODES * HID];
__device__ float g_C[N_EDGES];
__device__ uint32_t g_eaf[(size_t)NTILES * 8192];   // eattr, fragment-order fp16 (204.8 MB)

__device__ __forceinline__ float sspf(float x) {
    float sp = fmaxf(x, 0.0f) + log1pf(expf(-fabsf(x)));
    return sp - 0.69314718055994531f;
}

// pack two f32 into f16x2 (lo = first arg)
__device__ __forceinline__ uint32_t h2(float lo, float hi) {
    uint32_t r;
    asm("cvt.rn.f16x2.f32 %0, %1, %2;" : "=r"(r) : "f"(hi), "f"(lo));
    return r;
}

// ---------------- fp16 fragment-order smem layout (strides in 32-bit words) -------
// chunk = 32 k = 2 ksteps of m16n8k16.
// A-frag: [i-tile 0..7][ks 0..1][lane 0..31][w 0..3]  w = {a0,a1,a2,a3}
// B-frag: [pair 0..7][ks 0..1][lane 0..31][w 0..3]    w = {j0b0,j0b1,j1b0,j1b1}
// T-frag: [i-tile 0..7][ks 0..7][lane][w]             (resident 128x128 half tile)
#define KS_STR 132
#define AI_STR 264
#define AWORDS 2112
#define BP_STR 264
#define BWORDS 2112
#define TI_STR 1056
#define TWORDS 8448

#define EDGE_SMEM ((TWORDS + 2 * BWORDS) * 4)
#define NODE_SMEM ((TWORDS + 2 * AWORDS + 2 * BWORDS) * 4)
#define PLAIN_SMEM ((2 * AWORDS + 2 * BWORDS) * 4)

// ---------------- global->reg loaders (512 threads: 2 float4 each) ----------------
__device__ __forceinline__ void loadA_g(float4* r, const float* __restrict__ A,
                                        int mBase, int k0, int M, int K, int tid) {
#pragma unroll
    for (int i = 0; i < 2; i++) {
        int q = tid + (i << 9);
        int row = q >> 3, kq = (q & 7) << 2;
        int gm = mBase + row, gk = k0 + kq;
        r[i] = make_float4(0.f, 0.f, 0.f, 0.f);
        if (gm < M && gk < K)
            r[i] = *reinterpret_cast<const float4*>(A + (size_t)gm * K + gk);
    }
}
__device__ __forceinline__ void loadB_g(float4* r, const float* __restrict__ B,
                                        int k0, int K, int tid) {
#pragma unroll
    for (int i = 0; i < 2; i++) {
        int q = tid + (i << 9);
        int kr = q >> 5, nq = (q & 31) << 2;
        int gk = k0 + kr;
        r[i] = make_float4(0.f, 0.f, 0.f, 0.f);
        if (gk < K)
            r[i] = *reinterpret_cast<const float4*>(B + (size_t)gk * 128 + nq);
    }
}

// ---------------- reg->smem fp16 fragment-order stores ----------------
__device__ __forceinline__ void storeA_f(uint32_t* __restrict__ buf, const float4* r, int tid) {
#pragma unroll
    for (int i4 = 0; i4 < 2; i4++) {
        int q = tid + (i4 << 9);
        int row = q >> 3, kq = (q & 7) << 2;
        int iT = row >> 4, rl = row & 15;
        int g = rl & 7, hr = rl >> 3;
        int ks = kq >> 4, kl = kq & 15;
        int w = hr + ((kl & 8) ? 2 : 0);
        int t0 = (kl & 7) >> 1;
        uint32_t* p = buf + iT * AI_STR + ks * KS_STR + (g * 4 + t0) * 4 + w;
        p[0] = h2(r[i4].x, r[i4].y);
        p[4] = h2(r[i4].z, r[i4].w);
    }
}
__device__ __forceinline__ void storeB_f(uint32_t* __restrict__ buf, const float4* r, int tid) {
    __half* hb = reinterpret_cast<__half*>(buf);
#pragma unroll
    for (int i4 = 0; i4 < 2; i4++) {
        int q = tid + (i4 << 9);
        int kr = q >> 5, nq = (q & 31) << 2;
        int ks = kr >> 4, krl = kr & 15;
        int t = (krl & 7) >> 1;
        int hl = krl & 1;
        int wb = (krl >> 3) & 1;
        const float vv[4] = { r[i4].x, r[i4].y, r[i4].z, r[i4].w };
#pragma unroll
        for (int d = 0; d < 4; d++) {
            int n = nq + d;
            int pairI = n >> 4, jpar = (n >> 3) & 1, g0 = n & 7;
            int w = jpar * 2 + wb;
            int word = pairI * BP_STR + ks * KS_STR + (g0 * 4 + t) * 4 + w;
            hb[word * 2 + hl] = __float2half_rn(vv[d]);
        }
    }
}

// ---------------- mma: one 32-k chunk, smem A ----------------
template<int ISTR>
__device__ __forceinline__ void mma_chunk_f(const uint32_t* __restrict__ As,
                                            const uint32_t* __restrict__ Bs,
                                            float c[2][4][4], int wid, int lane)
{
    const uint32_t* Ab = As + ((wid & 3) * 2) * ISTR + lane * 4;
    const uint32_t* Bb = Bs + ((wid >> 2) * 2) * BP_STR + lane * 4;
#pragma unroll
    for (int ks = 0; ks < 2; ks++) {
        uint4 av[2], bv[2];
#pragma unroll
        for (int i = 0; i < 2; i++)
            av[i] = *reinterpret_cast<const uint4*>(Ab + i * ISTR + ks * KS_STR);
#pragma unroll
        for (int p = 0; p < 2; p++)
            bv[p] = *reinterpret_cast<const uint4*>(Bb + p * BP_STR + ks * KS_STR);
#pragma unroll
        for (int i = 0; i < 2; i++)
#pragma unroll
            for (int j = 0; j < 4; j++) {
                uint32_t b0 = (j & 1) ? bv[j >> 1].z : bv[j >> 1].x;
                uint32_t b1 = (j & 1) ? bv[j >> 1].w : bv[j >> 1].y;
                asm volatile(
                    "mma.sync.aligned.m16n8k16.row.col.f32.f16.f16.f32 "
                    "{%0,%1,%2,%3}, {%4,%5,%6,%7}, {%8,%9}, {%0,%1,%2,%3};\n"
                    : "+f"(c[i][j][0]), "+f"(c[i][j][1]), "+f"(c[i][j][2]), "+f"(c[i][j][3])
                    : "r"(av[i].x), "r"(av[i].y), "r"(av[i].z), "r"(av[i].w),
                      "r"(b0), "r"(b1));
            }
    }
}

// ---------------- mma: one 32-k chunk, A fragments in registers ----------------
__device__ __forceinline__ void mma_chunk_ra(const uint4* aC,   // [ks*2+i]
                                             const uint32_t* __restrict__ Bs,
                                             float c[2][4][4], int wid, int lane)
{
    const uint32_t* Bb = Bs + ((wid >> 2) * 2) * BP_STR + lane * 4;
#pragma unroll
    for (int ks = 0; ks < 2; ks++) {
        uint4 bv[2];
#pragma unroll
        for (int p = 0; p < 2; p++)
            bv[p] = *reinterpret_cast<const uint4*>(Bb + p * BP_STR + ks * KS_STR);
#pragma unroll
        for (int i = 0; i < 2; i++) {
            const uint4 av = aC[ks * 2 + i];
#pragma unroll
            for (int j = 0; j < 4; j++) {
                uint32_t b0 = (j & 1) ? bv[j >> 1].z : bv[j >> 1].x;
                uint32_t b1 = (j & 1) ? bv[j >> 1].w : bv[j >> 1].y;
                asm volatile(
                    "mma.sync.aligned.m16n8k16.row.col.f32.f16.f16.f32 "
                    "{%0,%1,%2,%3}, {%4,%5,%6,%7}, {%8,%9}, {%0,%1,%2,%3};\n"
                    : "+f"(c[i][j][0]), "+f"(c[i][j][1]), "+f"(c[i][j][2]), "+f"(c[i][j][3])
                    : "r"(av.x), "r"(av.y), "r"(av.z), "r"(av.w),
                      "r"(b0), "r"(b1));
            }
        }
    }
}

__device__ __forceinline__ void zero_c(float c[2][4][4]) {
#pragma unroll
    for (int i = 0; i < 2; i++)
#pragma unroll
        for (int j = 0; j < 4; j++)
#pragma unroll
            for (int v = 0; v < 4; v++) c[i][j][v] = 0.0f;
}

// store epilogue values (optionally ssp) into T fragment layout (half2 words)
__device__ __forceinline__ void store_T_frag(uint32_t* __restrict__ Tt, const float c[2][4][4],
                                             const float* bn, int wid, int g, int t,
                                             int warpN, bool doSsp)
{
    const int iTb = (wid & 3) * 2;
    const int ksBase = warpN >> 4;
#pragma unroll
    for (int i = 0; i < 2; i++)
#pragma unroll
        for (int half = 0; half < 2; half++)
#pragma unroll
            for (int j = 0; j < 4; j++) {
                float v0 = c[i][j][half * 2 + 0] + bn[j * 2 + 0];
                float v1 = c[i][j][half * 2 + 1] + bn[j * 2 + 1];
                if (doSsp) { v0 = sspf(v0); v1 = sspf(v1); }
                int ks = ksBase + (j >> 1);
                int w = half + 2 * (j & 1);
                Tt[(iTb + i) * TI_STR + ks * KS_STR + (g * 4 + t) * 4 + w] = h2(v0, v1);
            }
}

// ---------------- eattr pre-pack (tile-staged, coalesced both directions) ---------
// One CTA per 128-edge tile. Read: 4 threads x float4 per row (coalesced 1600B/row).
// Stage fragment-order in smem. Write: linear 8192-word dump (coalesced).
__global__ void __launch_bounds__(256) pack_eattr(const float* __restrict__ ea,
                                                  uint32_t* __restrict__ out) {
    __shared__ uint32_t sf[8192];
    const int tile = blockIdx.x;
    const int tid = threadIdx.x;
    // 256 threads: thread = (row 0..127) * 2 + (kHalf 0..1); each loads 16 floats
    const int row = tid >> 1;
    const int kh = tid & 1;          // k base = kh*64, but EC=100 so kh=1 covers 64..99
    const float* er = ea + ((size_t)tile * 128 + row) * EC;
    const int iT = row >> 4, rl = row & 15;
    const int g = rl & 7, hr = rl >> 3;
#pragma unroll
    for (int q = 0; q < 4; q++) {               // 4 float4 per thread
        int k = kh * 64 + q * 16;               // quad covers k..k+15? no: float4 = 4 floats
#pragma unroll
        for (int f4 = 0; f4 < 4; f4++) {
            int kq = kh * 64 + (q * 4 + f4) * 4;   // 4-float group base
            float4 v = make_float4(0.f, 0.f, 0.f, 0.f);
            if (kq < EC) {
                if (kq + 3 < EC)
                    v = *reinterpret_cast<const float4*>(er + kq);
                else {
                    v.x = er[kq];
                    if (kq + 1 < EC) v.y = er[kq + 1];
                    if (kq + 2 < EC) v.z = er[kq + 2];
                }
            }
            // fragment coords for (row, kq) and (row, kq+2)
            int ks = kq >> 4, kl = kq & 15;
            int w = hr + ((kl & 8) ? 2 : 0);
            int t0 = (kl & 7) >> 1;
            uint32_t* p = sf + iT * 1024 + ks * 128 + (g * 4 + t0) * 4 + w;
            p[0] = h2(v.x, v.y);
            p[4] = h2(v.z, v.w);
        }
        (void)k;
    }
    __syncthreads();
    uint32_t* o = out + (size_t)tile * 8192;
#pragma unroll
    for (int i = 0; i < 8; i++)
        *reinterpret_cast<uint4*>(o + (tid + i * 256) * 4) =
            *reinterpret_cast<const uint4*>(sf + (tid + i * 256) * 4);
}

// ---------------- fused edge kernel: GEMM+ssp+GEMM+mask + scatter -----------------
__global__ void __launch_bounds__(NT, 1) edge_fused(
    const uint32_t* __restrict__ eaf, const float* __restrict__ B1, const float* __restrict__ b1,
    const float* __restrict__ B2, const float* __restrict__ b2,
    const float* __restrict__ Cm, const int* __restrict__ src, const int* __restrict__ dst,
    const float* __restrict__ x, float* __restrict__ agg)
{
    extern __shared__ uint32_t sm[];
    uint32_t* Tt  = sm;
    uint32_t* Bs0 = sm + TWORDS;
    uint32_t* Bs1 = Bs0 + BWORDS;

    const int tid = threadIdx.x;
    const int wid = tid >> 5, lane = tid & 31;
    const int g = lane >> 2, t = lane & 3;
    const int warpM = (wid & 3) * 32, warpN = (wid >> 2) * 32;
    const int mBase = blockIdx.x * 128;

    float c[2][4][4];
    zero_c(c);
    float4 bR[2];

    // per-warp A fragment base in gmem (fragment-order, coalesced LDG.128)
    const uint32_t* Af = eaf + (size_t)blockIdx.x * 8192 + ((wid & 3) * 2) * 1024 + lane * 4;

    uint4 aC[4], aN[4];
#pragma unroll
    for (int s = 0; s < 2; s++)
#pragma unroll
        for (int i = 0; i < 2; i++)
            aC[s * 2 + i] = *reinterpret_cast<const uint4*>(Af + i * 1024 + s * 128);

    loadB_g(bR, B1, 0, EC, tid);
    storeB_f(Bs0, bR, tid);
    __syncthreads();
    for (int ch = 0; ch < 4; ch++) {
        if (ch < 3) {
#pragma unroll
            for (int s = 0; s < 2; s++)
#pragma unroll
                for (int i = 0; i < 2; i++)
                    aN[s * 2 + i] = *reinterpret_cast<const uint4*>(
                        Af + i * 1024 + ((ch + 1) * 2 + s) * 128);
            loadB_g(bR, B1, (ch + 1) * 32, EC, tid);
        }
        mma_chunk_ra(aC, (ch & 1) ? Bs1 : Bs0, c, wid, lane);
        if (ch < 3) {
            storeB_f(((ch + 1) & 1) ? Bs1 : Bs0, bR, tid);
#pragma unroll
            for (int q = 0; q < 4; q++) aC[q] = aN[q];
        }
        __syncthreads();
    }

    float bn1[8];
#pragma unroll
    for (int j = 0; j < 4; j++) {
        bn1[j * 2 + 0] = __ldg(b1 + warpN + j * 8 + t * 2 + 0);
        bn1[j * 2 + 1] = __ldg(b1 + warpN + j * 8 + t * 2 + 1);
    }
    store_T_frag(Tt, c, bn1, wid, g, t, warpN, true);
    zero_c(c);

    // stage 2: T (resident) @ B2
    loadB_g(bR, B2, 0, 128, tid);
    __syncthreads();
    storeB_f(Bs0, bR, tid);
    __syncthreads();
    for (int ch = 0; ch < 4; ch++) {
        if (ch < 3) loadB_g(bR, B2, (ch + 1) * 32, 128, tid);
        mma_chunk_f<TI_STR>(Tt + ch * 2 * KS_STR, (ch & 1) ? Bs1 : Bs0, c, wid, lane);
        if (ch < 3) storeB_f(((ch + 1) & 1) ? Bs1 : Bs0, bR, tid);
        __syncthreads();
    }

    // scatter epilogue (proven R7 form): guarded red.global.add.v2.f32
    float bn2[8];
#pragma unroll
    for (int j = 0; j < 4; j++) {
        bn2[j * 2 + 0] = __ldg(b2 + warpN + j * 8 + t * 2 + 0);
        bn2[j * 2 + 1] = __ldg(b2 + warpN + j * 8 + t * 2 + 1);
    }
#pragma unroll
    for (int i = 0; i < 2; i++)
#pragma unroll
        for (int half = 0; half < 2; half++) {
            const int e = mBase + warpM + i * 16 + g + half * 8;
            const float cmv = __ldg(Cm + e);
            if (cmv != 0.0f) {
                const int s = __ldg(src + e), d = __ldg(dst + e);
                const float* xr = x + (size_t)s * 128;
                float* ar = agg + (size_t)d * 128;
#pragma unroll
                for (int j = 0; j < 4; j++) {
                    const int col = warpN + j * 8 + t * 2;
                    float2 xv = *reinterpret_cast<const float2*>(xr + col);
                    float w0 = (c[i][j][half * 2 + 0] + bn2[j * 2 + 0]) * cmv;
                    float w1 = (c[i][j][half * 2 + 1] + bn2[j * 2 + 1]) * cmv;
                    float m0 = xv.x * w0, m1 = xv.y * w1;
                    asm volatile("red.global.add.v2.f32 [%0], {%1, %2};"
                                 :: "l"(ar + col), "f"(m0), "f"(m1) : "memory");
                }
            }
        }
}

// ---------------- fused node kernel ----------------
__global__ void __launch_bounds__(NT, 1) node_fused(
    const float* __restrict__ agg, const float* __restrict__ B1, const float* __restrict__ b1,
    const float* __restrict__ B2, const float* __restrict__ b2,
    float* __restrict__ h, const float* __restrict__ lin1, float* __restrict__ xOut)
{
    extern __shared__ uint32_t sm[];
    uint32_t* Tt  = sm;
    uint32_t* As0 = sm + TWORDS;
    uint32_t* As1 = As0 + AWORDS;
    uint32_t* Bs0 = As1 + AWORDS;
    uint32_t* Bs1 = Bs0 + BWORDS;

    const int tid = threadIdx.x;
    const int wid = tid >> 5, lane = tid & 31;
    const int g = lane >> 2, t = lane & 3;
    const int warpM = (wid & 3) * 32, warpN = (wid >> 2) * 32;
    const int mBase = blockIdx.x * 128;

    float c[2][4][4];
    zero_c(c);
    float4 aR[2], bR[2];

    // stage 1: agg @ B1 (K=128)
    loadA_g(aR, agg, mBase, 0, N_NODES, 128, tid);
    loadB_g(bR, B1, 0, 128, tid);
    storeA_f(As0, aR, tid);
    storeB_f(Bs0, bR, tid);
    __syncthreads();
    for (int ch = 0; ch < 4; ch++) {
        if (ch < 3) {
            loadA_g(aR, agg, mBase, (ch + 1) * 32, N_NODES, 128, tid);
            loadB_g(bR, B1, (ch + 1) * 32, 128, tid);
        }
        mma_chunk_f<AI_STR>((ch & 1) ? As1 : As0, (ch & 1) ? Bs1 : Bs0, c, wid, lane);
        if (ch < 3) {
            storeA_f(((ch + 1) & 1) ? As1 : As0, aR, tid);
            storeB_f(((ch + 1) & 1) ? Bs1 : Bs0, bR, tid);
        }
        __syncthreads();
    }

    float bn1[8];
#pragma unroll
    for (int j = 0; j < 4; j++) {
        bn1[j * 2 + 0] = __ldg(b1 + warpN + j * 8 + t * 2 + 0);
        bn1[j * 2 + 1] = __ldg(b1 + warpN + j * 8 + t * 2 + 1);
    }
    store_T_frag(Tt, c, bn1, wid, g, t, warpN, true);
    zero_c(c);

    // stage 2: T @ B2
    loadB_g(bR, B2, 0, 128, tid);
    __syncthreads();
    storeB_f(Bs0, bR, tid);
    __syncthreads();
    for (int ch = 0; ch < 4; ch++) {
        if (ch < 3) loadB_g(bR, B2, (ch + 1) * 32, 128, tid);
        mma_chunk_f<TI_STR>(Tt + ch * 2 * KS_STR, (ch & 1) ? Bs1 : Bs0, c, wid, lane);
        if (ch < 3) storeB_f(((ch + 1) & 1) ? Bs1 : Bs0, bR, tid);
        __syncthreads();
    }

    // stage-2 epilogue: h += residual; keep hnew resident in T-frag
    float bn2[8];
#pragma unroll
    for (int j = 0; j < 4; j++) {
        bn2[j * 2 + 0] = __ldg(b2 + warpN + j * 8 + t * 2 + 0);
        bn2[j * 2 + 1] = __ldg(b2 + warpN + j * 8 + t * 2 + 1);
    }
    const int iTb = (wid & 3) * 2;
    const int ksBase = warpN >> 4;
#pragma unroll
    for (int i = 0; i < 2; i++)
#pragma unroll
        for (int half = 0; half < 2; half++) {
            const int gm = mBase + warpM + i * 16 + g + half * 8;
            const bool ok = gm < N_NODES;
            float* hrow = h + (size_t)gm * 128;
#pragma unroll
            for (int j = 0; j < 4; j++) {
                const int col = warpN + j * 8 + t * 2;
                float v0 = c[i][j][half * 2 + 0] + bn2[j * 2 + 0];
                float v1 = c[i][j][half * 2 + 1] + bn2[j * 2 + 1];
                if (ok) {
                    float2 hv = *reinterpret_cast<const float2*>(hrow + col);
                    v0 += hv.x; v1 += hv.y;
                    *reinterpret_cast<float2*>(hrow + col) = make_float2(v0, v1);
                }
                int ks = ksBase + (j >> 1);
                int w = half + 2 * (j & 1);
                Tt[(iTb + i) * TI_STR + ks * KS_STR + (g * 4 + t) * 4 + w] = h2(v0, v1);
            }
        }

    // stage 3: xOut = hnew @ lin1 (next block's lin1)
    if (lin1 != nullptr) {
        zero_c(c);
        loadB_g(bR, lin1, 0, 128, tid);
        __syncthreads();
        storeB_f(Bs0, bR, tid);
        __syncthreads();
        for (int ch = 0; ch < 4; ch++) {
            if (ch < 3) loadB_g(bR, lin1, (ch + 1) * 32, 128, tid);
            mma_chunk_f<TI_STR>(Tt + ch * 2 * KS_STR, (ch & 1) ? Bs1 : Bs0, c, wid, lane);
            if (ch < 3) storeB_f(((ch + 1) & 1) ? Bs1 : Bs0, bR, tid);
            __syncthreads();
        }
#pragma unroll
        for (int i = 0; i < 2; i++)
#pragma unroll
            for (int half = 0; half < 2; half++) {
                const int gm = mBase + warpM + i * 16 + g + half * 8;
                if (gm < N_NODES) {
                    float* orow = xOut + (size_t)gm * 128;
#pragma unroll
                    for (int j = 0; j < 4; j++) {
                        const int col = warpN + j * 8 + t * 2;
                        *reinterpret_cast<float2*>(orow + col) =
                            make_float2(c[i][j][half * 2 + 0], c[i][j][half * 2 + 1]);
                    }
                }
            }
    }
}

// ---------------- plain GEMM (initial x = h @ lin1_0) ----------------
__global__ void __launch_bounds__(NT, 1) gemm_plain(
    const float* __restrict__ A, const float* __restrict__ B,
    float* __restrict__ out, int M)
{
    extern __shared__ uint32_t sm[];
    uint32_t* As0 = sm;
    uint32_t* As1 = As0 + AWORDS;
    uint32_t* Bs0 = As1 + AWORDS;
    uint32_t* Bs1 = Bs0 + BWORDS;

    const int tid = threadIdx.x;
    const int wid = tid >> 5, lane = tid & 31;
    const int g = lane >> 2, t = lane & 3;
    const int warpM = (wid & 3) * 32, warpN = (wid >> 2) * 32;
    const int mBase = blockIdx.x * 128;

    float c[2][4][4];
    zero_c(c);
    float4 aR[2], bR[2];
    loadA_g(aR, A, mBase, 0, M, 128, tid);
    loadB_g(bR, B, 0, 128, tid);
    storeA_f(As0, aR, tid);
    storeB_f(Bs0, bR, tid);
    __syncthreads();
    for (int ch = 0; ch < 4; ch++) {
        if (ch < 3) {
            loadA_g(aR, A, mBase, (ch + 1) * 32, M, 128, tid);
            loadB_g(bR, B, (ch + 1) * 32, 128, tid);
        }
        mma_chunk_f<AI_STR>((ch & 1) ? As1 : As0, (ch & 1) ? Bs1 : Bs0, c, wid, lane);
        if (ch < 3) {
            storeA_f(((ch + 1) & 1) ? As1 : As0, aR, tid);
            storeB_f(((ch + 1) & 1) ? Bs1 : Bs0, bR, tid);
        }
        __syncthreads();
    }
#pragma unroll
    for (int i = 0; i < 2; i++)
#pragma unroll
        for (int half = 0; half < 2; half++) {
            const int gm = mBase + warpM + i * 16 + g + half * 8;
            if (gm < M) {
                float* orow = out + (size_t)gm * 128;
#pragma unroll
                for (int j = 0; j < 4; j++) {
                    const int col = warpN + j * 8 + t * 2;
                    *reinterpret_cast<float2*>(orow + col) =
                        make_float2(c[i][j][half * 2 + 0], c[i][j][half * 2 + 1]);
                }
            }
        }
}

// ---------------- small kernels ----------------
__global__ void embed_kernel(const float* __restrict__ z, const float* __restrict__ w,
                             const float* __restrict__ b, float* __restrict__ h) {
    int n = blockIdx.x, j = threadIdx.x;
    const float* zr = z + (size_t)n * (IN_DIM + HID);
    float acc = b[j] + zr[IN_DIM + j];
#pragma unroll
    for (int k = 0; k < IN_DIM; k++) acc = fmaf(zr[k], w[k * HID + j], acc);
    h[(size_t)n * HID + j] = acc;
}

__global__ void cmask_kernel(const float* __restrict__ len, float* __restrict__ C) {
    int e = blockIdx.x * 256 + threadIdx.x;
    if (e < N_EDGES) {
        float l = len[e];
        C[e] = (l <= 10.0f && l >= 0.0f) ? 1.0f : 0.0f;
    }
}

__global__ void zero_kernel(float4* __restrict__ p, int n4) {
    int i = blockIdx.x * 256 + threadIdx.x;
    if (i < n4) p[i] = make_float4(0.f, 0.f, 0.f, 0.f);
}

// ---------------- host launch ----------------
extern "C" void kernel_launch(void* const* d_in, const int* in_sizes, int n_in,
                              void* d_out, int out_size) {
    const float* z      = (const float*)d_in[0];
    const int*   ei     = (const int*)  d_in[1];
    const float* elen   = (const float*)d_in[2];
    const float* eattr  = (const float*)d_in[3];
    const float* emb_w  = (const float*)d_in[4];
    const float* emb_b  = (const float*)d_in[5];
    const float* lin1_w = (const float*)d_in[6];
    const float* nn_w1  = (const float*)d_in[7];
    const float* nn_b1  = (const float*)d_in[8];
    const float* nn_w2  = (const float*)d_in[9];
    const float* nn_b2  = (const float*)d_in[10];
    const float* lin2_w = (const float*)d_in[11];
    const float* lin2_b = (const float*)d_in[12];
    const float* lin_w  = (const float*)d_in[13];
    const float* lin_b  = (const float*)d_in[14];
    float* h = (float*)d_out;

    float *px, *pagg, *pC;
    uint32_t* peaf;
    cudaGetSymbolAddress((void**)&px,   g_x);
    cudaGetSymbolAddress((void**)&pagg, g_agg);
    cudaGetSymbolAddress((void**)&pC,   g_C);
    cudaGetSymbolAddress((void**)&peaf, g_eaf);

    cudaFuncSetAttribute(edge_fused, cudaFuncAttributeMaxDynamicSharedMemorySize, EDGE_SMEM);
    cudaFuncSetAttribute(node_fused, cudaFuncAttributeMaxDynamicSharedMemorySize, NODE_SMEM);
    cudaFuncSetAttribute(gemm_plain, cudaFuncAttributeMaxDynamicSharedMemorySize, PLAIN_SMEM);

    const int* src = ei;
    const int* dst = ei + N_EDGES;

    embed_kernel<<<N_NODES, HID>>>(z, emb_w, emb_b, h);
    cmask_kernel<<<(N_EDGES + 255) / 256, 256>>>(elen, pC);
    pack_eattr<<<NTILES, 256>>>(eattr, peaf);

    const int nodeTiles = (N_NODES + 127) / 128;   // 391
    const int aggN4 = N_NODES * HID / 4;

    gemm_plain<<<nodeTiles, NT, PLAIN_SMEM>>>(h, lin1_w, px, N_NODES);

    for (int i = 0; i < N_BLOCKS; i++) {
        zero_kernel<<<(aggN4 + 255) / 256, 256>>>((float4*)pagg, aggN4);
        edge_fused<<<NTILES, NT, EDGE_SMEM>>>(
            peaf, nn_w1 + (size_t)i * EC * HID, nn_b1 + (size_t)i * HID,
            nn_w2 + (size_t)i * HID * HID, nn_b2 + (size_t)i * HID,
            pC, src, dst, px, pagg);
        const float* lin1next = (i + 1 < N_BLOCKS) ? (lin1_w + (size_t)(i + 1) * HID * HID) : nullptr;
        node_fused<<<nodeTiles, NT, NODE_SMEM>>>(
            pagg, lin2_w + (size_t)i * HID * HID, lin2_b + (size_t)i * HID,
            lin_w + (size_t)i * HID * HID, lin_b + (size_t)i * HID,
            h, lin1next, px);
    }
}

// round 10
// speedup vs baseline: 1.1673x; 1.0811x over previous
#include <cuda_runtime.h>
#include <cuda_fp16.h>
#include <cstdint>
#include <math.h>

#define N_NODES 50000
#define N_EDGES 800000
#define HID 128
#define EC 100
#define IN_DIM 5
#define N_BLOCKS 6
#define NT 512
#define NTILES 6250

// ---------------- scratch (device globals; no runtime allocation) ----------------
__device__ float g_x[N_NODES * HID];
__device__ float g_agg[N_NODES * HID];
__device__ float g_C[N_EDGES];
__device__ uint32_t g_eaf[(size_t)NTILES * 8192];   // eattr fragment-order fp16 (204.8 MB)
// weight tensors in fragment-order fp16: [6 blocks][4 chunks][2048 words]
__device__ uint32_t g_w1f[6 * 8192];
__device__ uint32_t g_w2f[6 * 8192];
__device__ uint32_t g_l2f[6 * 8192];
__device__ uint32_t g_lf [6 * 8192];
__device__ uint32_t g_l1f[6 * 8192];

__device__ __forceinline__ float sspf(float x) {
    float sp = fmaxf(x, 0.0f) + log1pf(expf(-fabsf(x)));
    return sp - 0.69314718055994531f;
}

__device__ __forceinline__ uint32_t h2(float lo, float hi) {
    uint32_t r;
    asm("cvt.rn.f16x2.f32 %0, %1, %2;" : "=r"(r) : "f"(hi), "f"(lo));
    return r;
}

// ---------------- fragment layout constants ----------------
// smem (padded): A/T-frag strides in words
#define KS_STR 132
#define AI_STR 264
#define AWORDS 2112
#define TI_STR 1056
#define TWORDS 8448
// gmem B-frag (unpadded): chunk=2048 words, pair stride 256, ks stride 128

#define EDGE_SMEM (TWORDS * 4)
#define NODE_SMEM ((TWORDS + 2 * AWORDS) * 4)
#define PLAIN_SMEM ((2 * AWORDS) * 4)

// ---------------- weight pre-pack: row-major f32 [6][K][128] -> frag fp16 ---------
__global__ void __launch_bounds__(256) pack_w(
    const float* __restrict__ w1, const float* __restrict__ w2,
    const float* __restrict__ l2, const float* __restrict__ l,
    const float* __restrict__ l1,
    uint32_t* __restrict__ o1, uint32_t* __restrict__ o2,
    uint32_t* __restrict__ o3, uint32_t* __restrict__ o4,
    uint32_t* __restrict__ o5)
{
    const float* W; uint32_t* O; int K;
    switch (blockIdx.y) {
        case 0: W = w1; O = o1; K = EC;  break;
        case 1: W = w2; O = o2; K = 128; break;
        case 2: W = l2; O = o3; K = 128; break;
        case 3: W = l;  O = o4; K = 128; break;
        default: W = l1; O = o5; K = 128; break;
    }
    int idx = blockIdx.x * 256 + threadIdx.x;
    if (idx >= 6 * 8192) return;
    int blk = idx >> 13;
    int r = idx & 8191;
    int ch = r >> 11;
    int r2 = r & 2047;
    int pair = r2 >> 8;
    int ks = (r2 >> 7) & 1;
    int lane = (r2 >> 2) & 31;
    int w = r2 & 3;
    int g0 = lane >> 2, t = lane & 3;
    int jpar = w >> 1, wb = w & 1;
    int k = ch * 32 + ks * 16 + wb * 8 + t * 2;
    int n = pair * 16 + jpar * 8 + g0;
    const float* Wb = W + (size_t)blk * K * 128;
    float v0 = (k < K) ? Wb[(size_t)k * 128 + n] : 0.f;
    float v1 = (k + 1 < K) ? Wb[(size_t)(k + 1) * 128 + n] : 0.f;
    O[idx] = h2(v0, v1);
}

// ---------------- global->reg A loader + reg->smem A-frag store ----------------
__device__ __forceinline__ void loadA_g(float4* r, const float* __restrict__ A,
                                        int mBase, int k0, int M, int K, int tid) {
#pragma unroll
    for (int i = 0; i < 2; i++) {
        int q = tid + (i << 9);
        int row = q >> 3, kq = (q & 7) << 2;
        int gm = mBase + row, gk = k0 + kq;
        r[i] = make_float4(0.f, 0.f, 0.f, 0.f);
        if (gm < M && gk < K)
            r[i] = *reinterpret_cast<const float4*>(A + (size_t)gm * K + gk);
    }
}
__device__ __forceinline__ void storeA_f(uint32_t* __restrict__ buf, const float4* r, int tid) {
#pragma unroll
    for (int i4 = 0; i4 < 2; i4++) {
        int q = tid + (i4 << 9);
        int row = q >> 3, kq = (q & 7) << 2;
        int iT = row >> 4, rl = row & 15;
        int g = rl & 7, hr = rl >> 3;
        int ks = kq >> 4, kl = kq & 15;
        int w = hr + ((kl & 8) ? 2 : 0);
        int t0 = (kl & 7) >> 1;
        uint32_t* p = buf + iT * AI_STR + ks * KS_STR + (g * 4 + t0) * 4 + w;
        p[0] = h2(r[i4].x, r[i4].y);
        p[4] = h2(r[i4].z, r[i4].w);
    }
}

// ---------------- mma cores ----------------
__device__ __forceinline__ void mma8(float c[4][4], const uint4 av, const uint4* bv) {
#pragma unroll
    for (int j = 0; j < 4; j++) {
        uint32_t b0 = (j & 1) ? bv[j >> 1].z : bv[j >> 1].x;
        uint32_t b1 = (j & 1) ? bv[j >> 1].w : bv[j >> 1].y;
        asm volatile(
            "mma.sync.aligned.m16n8k16.row.col.f32.f16.f16.f32 "
            "{%0,%1,%2,%3}, {%4,%5,%6,%7}, {%8,%9}, {%0,%1,%2,%3};\n"
            : "+f"(c[j][0]), "+f"(c[j][1]), "+f"(c[j][2]), "+f"(c[j][3])
            : "r"(av.x), "r"(av.y), "r"(av.z), "r"(av.w), "r"(b0), "r"(b1));
    }
}

// chunk: A fragments in registers, B fragments direct from gmem (L2-resident)
__device__ __forceinline__ void mma_chunk_ra_g(const uint4* aC, const uint32_t* __restrict__ Bg,
                                               float c[2][4][4], int wid, int lane)
{
    const uint32_t* Bb = Bg + ((wid >> 2) * 2) * 256 + lane * 4;
    uint4 bv[2][2];
#pragma unroll
    for (int ks = 0; ks < 2; ks++)
#pragma unroll
        for (int p = 0; p < 2; p++)
            bv[ks][p] = *reinterpret_cast<const uint4*>(Bb + p * 256 + ks * 128);
#pragma unroll
    for (int ks = 0; ks < 2; ks++)
#pragma unroll
        for (int i = 0; i < 2; i++)
            mma8(c[i], aC[ks * 2 + i], bv[ks]);
}

// chunk: A fragments from smem (stride ISTR), B from gmem
template<int ISTR>
__device__ __forceinline__ void mma_chunk_sg(const uint32_t* __restrict__ As,
                                             const uint32_t* __restrict__ Bg,
                                             float c[2][4][4], int wid, int lane)
{
    const uint32_t* Ab = As + ((wid & 3) * 2) * ISTR + lane * 4;
    const uint32_t* Bb = Bg + ((wid >> 2) * 2) * 256 + lane * 4;
    uint4 bv[2][2];
#pragma unroll
    for (int ks = 0; ks < 2; ks++)
#pragma unroll
        for (int p = 0; p < 2; p++)
            bv[ks][p] = *reinterpret_cast<const uint4*>(Bb + p * 256 + ks * 128);
#pragma unroll
    for (int ks = 0; ks < 2; ks++) {
        uint4 av[2];
#pragma unroll
        for (int i = 0; i < 2; i++)
            av[i] = *reinterpret_cast<const uint4*>(Ab + i * ISTR + ks * KS_STR);
#pragma unroll
        for (int i = 0; i < 2; i++)
            mma8(c[i], av[i], bv[ks]);
    }
}

__device__ __forceinline__ void zero_c(float c[2][4][4]) {
#pragma unroll
    for (int i = 0; i < 2; i++)
#pragma unroll
        for (int j = 0; j < 4; j++)
#pragma unroll
            for (int v = 0; v < 4; v++) c[i][j][v] = 0.0f;
}

// store epilogue values (optionally ssp) into T fragment layout (half2 words)
__device__ __forceinline__ void store_T_frag(uint32_t* __restrict__ Tt, const float c[2][4][4],
                                             const float* bn, int wid, int g, int t,
                                             int warpN, bool doSsp)
{
    const int iTb = (wid & 3) * 2;
    const int ksBase = warpN >> 4;
#pragma unroll
    for (int i = 0; i < 2; i++)
#pragma unroll
        for (int half = 0; half < 2; half++)
#pragma unroll
            for (int j = 0; j < 4; j++) {
                float v0 = c[i][j][half * 2 + 0] + bn[j * 2 + 0];
                float v1 = c[i][j][half * 2 + 1] + bn[j * 2 + 1];
                if (doSsp) { v0 = sspf(v0); v1 = sspf(v1); }
                int ks = ksBase + (j >> 1);
                int w = half + 2 * (j & 1);
                Tt[(iTb + i) * TI_STR + ks * KS_STR + (g * 4 + t) * 4 + w] = h2(v0, v1);
            }
}

// ---------------- eattr pre-pack (tile-staged, coalesced; proven R9) --------------
__global__ void __launch_bounds__(256) pack_eattr(const float* __restrict__ ea,
                                                  uint32_t* __restrict__ out) {
    __shared__ uint32_t sf[8192];
    const int tile = blockIdx.x;
    const int tid = threadIdx.x;
    const int row = tid >> 1;
    const int kh = tid & 1;
    const float* er = ea + ((size_t)tile * 128 + row) * EC;
    const int iT = row >> 4, rl = row & 15;
    const int g = rl & 7, hr = rl >> 3;
#pragma unroll
    for (int q = 0; q < 4; q++) {
#pragma unroll
        for (int f4 = 0; f4 < 4; f4++) {
            int kq = kh * 64 + (q * 4 + f4) * 4;
            float4 v = make_float4(0.f, 0.f, 0.f, 0.f);
            if (kq < EC) {
                if (kq + 3 < EC)
                    v = *reinterpret_cast<const float4*>(er + kq);
                else {
                    v.x = er[kq];
                    if (kq + 1 < EC) v.y = er[kq + 1];
                    if (kq + 2 < EC) v.z = er[kq + 2];
                }
            }
            int ks = kq >> 4, kl = kq & 15;
            int w = hr + ((kl & 8) ? 2 : 0);
            int t0 = (kl & 7) >> 1;
            uint32_t* p = sf + iT * 1024 + ks * 128 + (g * 4 + t0) * 4 + w;
            p[0] = h2(v.x, v.y);
            p[4] = h2(v.z, v.w);
        }
    }
    __syncthreads();
    uint32_t* o = out + (size_t)tile * 8192;
#pragma unroll
    for (int i = 0; i < 8; i++)
        *reinterpret_cast<uint4*>(o + (tid + i * 256) * 4) =
            *reinterpret_cast<const uint4*>(sf + (tid + i * 256) * 4);
}

// ---------------- fused edge kernel ----------------
__global__ void __launch_bounds__(NT, 1) edge_fused(
    const uint32_t* __restrict__ eaf,
    const uint32_t* __restrict__ B1g, const float* __restrict__ b1,
    const uint32_t* __restrict__ B2g, const float* __restrict__ b2,
    const float* __restrict__ Cm, const int* __restrict__ src, const int* __restrict__ dst,
    const float* __restrict__ x, float* __restrict__ agg)
{
    extern __shared__ uint32_t sm[];
    uint32_t* Tt = sm;

    const int tid = threadIdx.x;
    const int wid = tid >> 5, lane = tid & 31;
    const int g = lane >> 2, t = lane & 3;
    const int warpM = (wid & 3) * 32, warpN = (wid >> 2) * 32;
    const int mBase = blockIdx.x * 128;

    float c[2][4][4];
    zero_c(c);

    // stage 1: all-register, no smem, no syncs
    const uint32_t* Af = eaf + (size_t)blockIdx.x * 8192 + ((wid & 3) * 2) * 1024 + lane * 4;
    uint4 aC[4], aN[4];
#pragma unroll
    for (int s = 0; s < 2; s++)
#pragma unroll
        for (int i = 0; i < 2; i++)
            aC[s * 2 + i] = *reinterpret_cast<const uint4*>(Af + i * 1024 + s * 128);
#pragma unroll 1
    for (int ch = 0; ch < 4; ch++) {
        if (ch < 3) {
#pragma unroll
            for (int s = 0; s < 2; s++)
#pragma unroll
                for (int i = 0; i < 2; i++)
                    aN[s * 2 + i] = *reinterpret_cast<const uint4*>(
                        Af + i * 1024 + ((ch + 1) * 2 + s) * 128);
        }
        mma_chunk_ra_g(aC, B1g + ch * 2048, c, wid, lane);
        if (ch < 3) {
#pragma unroll
            for (int q = 0; q < 4; q++) aC[q] = aN[q];
        }
    }

    float bn1[8];
#pragma unroll
    for (int j = 0; j < 4; j++) {
        bn1[j * 2 + 0] = __ldg(b1 + warpN + j * 8 + t * 2 + 0);
        bn1[j * 2 + 1] = __ldg(b1 + warpN + j * 8 + t * 2 + 1);
    }
    store_T_frag(Tt, c, bn1, wid, g, t, warpN, true);
    zero_c(c);
    __syncthreads();   // T visible to all warps

    // stage 2: T (smem) @ B2 (gmem frags)
#pragma unroll 1
    for (int ch = 0; ch < 4; ch++)
        mma_chunk_sg<TI_STR>(Tt + ch * 2 * KS_STR, B2g + ch * 2048, c, wid, lane);

    // scatter epilogue: guarded red.global.add.v2.f32
    float bn2[8];
#pragma unroll
    for (int j = 0; j < 4; j++) {
        bn2[j * 2 + 0] = __ldg(b2 + warpN + j * 8 + t * 2 + 0);
        bn2[j * 2 + 1] = __ldg(b2 + warpN + j * 8 + t * 2 + 1);
    }
#pragma unroll
    for (int i = 0; i < 2; i++)
#pragma unroll
        for (int half = 0; half < 2; half++) {
            const int e = mBase + warpM + i * 16 + g + half * 8;
            const float cmv = __ldg(Cm + e);
            if (cmv != 0.0f) {
                const int s = __ldg(src + e), d = __ldg(dst + e);
                const float* xr = x + (size_t)s * 128;
                float* ar = agg + (size_t)d * 128;
#pragma unroll
                for (int j = 0; j < 4; j++) {
                    const int col = warpN + j * 8 + t * 2;
                    float2 xv = *reinterpret_cast<const float2*>(xr + col);
                    float w0 = (c[i][j][half * 2 + 0] + bn2[j * 2 + 0]) * cmv;
                    float w1 = (c[i][j][half * 2 + 1] + bn2[j * 2 + 1]) * cmv;
                    float m0 = xv.x * w0, m1 = xv.y * w1;
                    asm volatile("red.global.add.v2.f32 [%0], {%1, %2};"
                                 :: "l"(ar + col), "f"(m0), "f"(m1) : "memory");
                }
            }
        }
}

// ---------------- fused node kernel ----------------
__global__ void __launch_bounds__(NT, 1) node_fused(
    const float* __restrict__ agg,
    const uint32_t* __restrict__ B1g, const float* __restrict__ b1,
    const uint32_t* __restrict__ B2g, const float* __restrict__ b2,
    float* __restrict__ h, const uint32_t* __restrict__ B3g, float* __restrict__ xOut)
{
    extern __shared__ uint32_t sm[];
    uint32_t* Tt  = sm;
    uint32_t* As0 = sm + TWORDS;
    uint32_t* As1 = As0 + AWORDS;

    const int tid = threadIdx.x;
    const int wid = tid >> 5, lane = tid & 31;
    const int g = lane >> 2, t = lane & 3;
    const int warpM = (wid & 3) * 32, warpN = (wid >> 2) * 32;
    const int mBase = blockIdx.x * 128;

    float c[2][4][4];
    zero_c(c);
    float4 aR[2];

    // stage 1: agg (smem-staged A) @ B1 (gmem frags)
    loadA_g(aR, agg, mBase, 0, N_NODES, 128, tid);
    storeA_f(As0, aR, tid);
    __syncthreads();
#pragma unroll 1
    for (int ch = 0; ch < 4; ch++) {
        if (ch < 3) loadA_g(aR, agg, mBase, (ch + 1) * 32, N_NODES, 128, tid);
        mma_chunk_sg<AI_STR>((ch & 1) ? As1 : As0, B1g + ch * 2048, c, wid, lane);
        if (ch < 3) storeA_f(((ch + 1) & 1) ? As1 : As0, aR, tid);
        __syncthreads();
    }

    float bn1[8];
#pragma unroll
    for (int j = 0; j < 4; j++) {
        bn1[j * 2 + 0] = __ldg(b1 + warpN + j * 8 + t * 2 + 0);
        bn1[j * 2 + 1] = __ldg(b1 + warpN + j * 8 + t * 2 + 1);
    }
    store_T_frag(Tt, c, bn1, wid, g, t, warpN, true);
    zero_c(c);
    __syncthreads();

    // stage 2: T @ B2 (gmem frags), no syncs
#pragma unroll 1
    for (int ch = 0; ch < 4; ch++)
        mma_chunk_sg<TI_STR>(Tt + ch * 2 * KS_STR, B2g + ch * 2048, c, wid, lane);
    __syncthreads();   // all warps done reading Tt before epilogue overwrites it

    // stage-2 epilogue: h += residual; keep hnew resident in T-frag
    float bn2[8];
#pragma unroll
    for (int j = 0; j < 4; j++) {
        bn2[j * 2 + 0] = __ldg(b2 + warpN + j * 8 + t * 2 + 0);
        bn2[j * 2 + 1] = __ldg(b2 + warpN + j * 8 + t * 2 + 1);
    }
    const int iTb = (wid & 3) * 2;
    const int ksBase = warpN >> 4;
#pragma unroll
    for (int i = 0; i < 2; i++)
#pragma unroll
        for (int half = 0; half < 2; half++) {
            const int gm = mBase + warpM + i * 16 + g + half * 8;
            const bool ok = gm < N_NODES;
            float* hrow = h + (size_t)gm * 128;
#pragma unroll
            for (int j = 0; j < 4; j++) {
                const int col = warpN + j * 8 + t * 2;
                float v0 = c[i][j][half * 2 + 0] + bn2[j * 2 + 0];
                float v1 = c[i][j][half * 2 + 1] + bn2[j * 2 + 1];
                if (ok) {
                    float2 hv = *reinterpret_cast<const float2*>(hrow + col);
                    v0 += hv.x; v1 += hv.y;
                    *reinterpret_cast<float2*>(hrow + col) = make_float2(v0, v1);
                }
                int ks = ksBase + (j >> 1);
                int w = half + 2 * (j & 1);
                Tt[(iTb + i) * TI_STR + ks * KS_STR + (g * 4 + t) * 4 + w] = h2(v0, v1);
            }
        }

    // stage 3: xOut = hnew @ lin1next (gmem frags)
    if (B3g != nullptr) {
        zero_c(c);
        __syncthreads();   // hnew T-frag complete
#pragma unroll 1
        for (int ch = 0; ch < 4; ch++)
            mma_chunk_sg<TI_STR>(Tt + ch * 2 * KS_STR, B3g + ch * 2048, c, wid, lane);
#pragma unroll
        for (int i = 0; i < 2; i++)
#pragma unroll
            for (int half = 0; half < 2; half++) {
                const int gm = mBase + warpM + i * 16 + g + half * 8;
                if (gm < N_NODES) {
                    float* orow = xOut + (size_t)gm * 128;
#pragma unroll
                    for (int j = 0; j < 4; j++) {
                        const int col = warpN + j * 8 + t * 2;
                        *reinterpret_cast<float2*>(orow + col) =
                            make_float2(c[i][j][half * 2 + 0], c[i][j][half * 2 + 1]);
                    }
                }
            }
    }
}

// ---------------- plain GEMM (initial x = h @ lin1_0) ----------------
__global__ void __launch_bounds__(NT, 1) gemm_plain(
    const float* __restrict__ A, const uint32_t* __restrict__ Bg,
    float* __restrict__ out, int M)
{
    extern __shared__ uint32_t sm[];
    uint32_t* As0 = sm;
    uint32_t* As1 = As0 + AWORDS;

    const int tid = threadIdx.x;
    const int wid = tid >> 5, lane = tid & 31;
    const int g = lane >> 2, t = lane & 3;
    const int warpM = (wid & 3) * 32, warpN = (wid >> 2) * 32;
    const int mBase = blockIdx.x * 128;

    float c[2][4][4];
    zero_c(c);
    float4 aR[2];
    loadA_g(aR, A, mBase, 0, M, 128, tid);
    storeA_f(As0, aR, tid);
    __syncthreads();
#pragma unroll 1
    for (int ch = 0; ch < 4; ch++) {
        if (ch < 3) loadA_g(aR, A, mBase, (ch + 1) * 32, M, 128, tid);
        mma_chunk_sg<AI_STR>((ch & 1) ? As1 : As0, Bg + ch * 2048, c, wid, lane);
        if (ch < 3) storeA_f(((ch + 1) & 1) ? As1 : As0, aR, tid);
        __syncthreads();
    }
#pragma unroll
    for (int i = 0; i < 2; i++)
#pragma unroll
        for (int half = 0; half < 2; half++) {
            const int gm = mBase + warpM + i * 16 + g + half * 8;
            if (gm < M) {
                float* orow = out + (size_t)gm * 128;
#pragma unroll
                for (int j = 0; j < 4; j++) {
                    const int col = warpN + j * 8 + t * 2;
                    *reinterpret_cast<float2*>(orow + col) =
                        make_float2(c[i][j][half * 2 + 0], c[i][j][half * 2 + 1]);
                }
            }
        }
}

// ---------------- small kernels ----------------
__global__ void embed_kernel(const float* __restrict__ z, const float* __restrict__ w,
                             const float* __restrict__ b, float* __restrict__ h) {
    int n = blockIdx.x, j = threadIdx.x;
    const float* zr = z + (size_t)n * (IN_DIM + HID);
    float acc = b[j] + zr[IN_DIM + j];
#pragma unroll
    for (int k = 0; k < IN_DIM; k++) acc = fmaf(zr[k], w[k * HID + j], acc);
    h[(size_t)n * HID + j] = acc;
}

__global__ void cmask_kernel(const float* __restrict__ len, float* __restrict__ C) {
    int e = blockIdx.x * 256 + threadIdx.x;
    if (e < N_EDGES) {
        float l = len[e];
        C[e] = (l <= 10.0f && l >= 0.0f) ? 1.0f : 0.0f;
    }
}

__global__ void zero_kernel(float4* __restrict__ p, int n4) {
    int i = blockIdx.x * 256 + threadIdx.x;
    if (i < n4) p[i] = make_float4(0.f, 0.f, 0.f, 0.f);
}

// ---------------- host launch ----------------
extern "C" void kernel_launch(void* const* d_in, const int* in_sizes, int n_in,
                              void* d_out, int out_size) {
    const float* z      = (const float*)d_in[0];
    const int*   ei     = (const int*)  d_in[1];
    const float* elen   = (const float*)d_in[2];
    const float* eattr  = (const float*)d_in[3];
    const float* emb_w  = (const float*)d_in[4];
    const float* emb_b  = (const float*)d_in[5];
    const float* lin1_w = (const float*)d_in[6];
    const float* nn_w1  = (const float*)d_in[7];
    const float* nn_b1  = (const float*)d_in[8];
    const float* nn_w2  = (const float*)d_in[9];
    const float* nn_b2  = (const float*)d_in[10];
    const float* lin2_w = (const float*)d_in[11];
    const float* lin2_b = (const float*)d_in[12];
    const float* lin_w  = (const float*)d_in[13];
    const float* lin_b  = (const float*)d_in[14];
    float* h = (float*)d_out;

    float *px, *pagg, *pC;
    uint32_t *peaf, *pw1, *pw2, *pl2, *pl, *pl1;
    cudaGetSymbolAddress((void**)&px,   g_x);
    cudaGetSymbolAddress((void**)&pagg, g_agg);
    cudaGetSymbolAddress((void**)&pC,   g_C);
    cudaGetSymbolAddress((void**)&peaf, g_eaf);
    cudaGetSymbolAddress((void**)&pw1,  g_w1f);
    cudaGetSymbolAddress((void**)&pw2,  g_w2f);
    cudaGetSymbolAddress((void**)&pl2,  g_l2f);
    cudaGetSymbolAddress((void**)&pl,   g_lf);
    cudaGetSymbolAddress((void**)&pl1,  g_l1f);

    cudaFuncSetAttribute(edge_fused, cudaFuncAttributeMaxDynamicSharedMemorySize, EDGE_SMEM);
    cudaFuncSetAttribute(node_fused, cudaFuncAttributeMaxDynamicSharedMemorySize, NODE_SMEM);
    cudaFuncSetAttribute(gemm_plain, cudaFuncAttributeMaxDynamicSharedMemorySize, PLAIN_SMEM);

    const int* src = ei;
    const int* dst = ei + N_EDGES;

    embed_kernel<<<N_NODES, HID>>>(z, emb_w, emb_b, h);
    cmask_kernel<<<(N_EDGES + 255) / 256, 256>>>(elen, pC);
    pack_eattr<<<NTILES, 256>>>(eattr, peaf);
    {
        dim3 gw((6 * 8192 + 255) / 256, 5);
        pack_w<<<gw, 256>>>(nn_w1, nn_w2, lin2_w, lin_w, lin1_w, pw1, pw2, pl2, pl, pl1);
    }

    const int nodeTiles = (N_NODES + 127) / 128;   // 391
    const int aggN4 = N_NODES * HID / 4;

    gemm_plain<<<nodeTiles, NT, PLAIN_SMEM>>>(h, pl1, px, N_NODES);

    for (int i = 0; i < N_BLOCKS; i++) {
        zero_kernel<<<(aggN4 + 255) / 256, 256>>>((float4*)pagg, aggN4);
        edge_fused<<<NTILES, NT, EDGE_SMEM>>>(
            peaf, pw1 + i * 8192, nn_b1 + (size_t)i * HID,
            pw2 + i * 8192, nn_b2 + (size_t)i * HID,
            pC, src, dst, px, pagg);
        const uint32_t* lin1next = (i + 1 < N_BLOCKS) ? (pl1 + (i + 1) * 8192) : nullptr;
        node_fused<<<nodeTiles, NT, NODE_SMEM>>>(
            pagg, pl2 + i * 8192, lin2_b + (size_t)i * HID,
            pl + i * 8192, lin_b + (size_t)i * HID,
            h, lin1next, px);
    }
}

// round 11
// speedup vs baseline: 1.3343x; 1.1431x over previous
#include <cuda_runtime.h>
#include <cuda_fp16.h>
#include <cstdint>
#include <math.h>

#define N_NODES 50000
#define N_EDGES 800000
#define HID 128
#define EC 100
#define IN_DIM 5
#define N_BLOCKS 6
#define NT 512
#define NTILES 6250

// ---------------- scratch (device globals; no runtime allocation) ----------------
__device__ float g_x[N_NODES * HID];
__device__ float g_agg[N_NODES * HID];
__device__ float g_C[N_EDGES];
__device__ uint32_t g_eaf[(size_t)NTILES * 8192];   // eattr fragment-order fp16
__device__ uint32_t g_w1f[6 * 8192];
__device__ uint32_t g_w2f[6 * 8192];
__device__ uint32_t g_l2f[6 * 8192];
__device__ uint32_t g_lf [6 * 8192];
__device__ uint32_t g_l1f[6 * 8192];

__device__ __forceinline__ float sspf(float x) {
    float sp = fmaxf(x, 0.0f) + log1pf(expf(-fabsf(x)));
    return sp - 0.69314718055994531f;
}

__device__ __forceinline__ uint32_t h2(float lo, float hi) {
    uint32_t r;
    asm("cvt.rn.f16x2.f32 %0, %1, %2;" : "=r"(r) : "f"(hi), "f"(lo));
    return r;
}

// ---------------- fragment layout constants ----------------
#define KS_STR 132
#define AI_STR 264
#define AWORDS 2112
#define TI_STR 1056
#define TWORDS 8448

#define EDGE_SMEM (TWORDS * 4)
#define NODE_SMEM ((TWORDS + 2 * AWORDS) * 4)
#define PLAIN_SMEM ((2 * AWORDS) * 4)

// ---------------- weight pre-pack ----------------
__global__ void __launch_bounds__(256) pack_w(
    const float* __restrict__ w1, const float* __restrict__ w2,
    const float* __restrict__ l2, const float* __restrict__ l,
    const float* __restrict__ l1,
    uint32_t* __restrict__ o1, uint32_t* __restrict__ o2,
    uint32_t* __restrict__ o3, uint32_t* __restrict__ o4,
    uint32_t* __restrict__ o5)
{
    const float* W; uint32_t* O; int K;
    switch (blockIdx.y) {
        case 0: W = w1; O = o1; K = EC;  break;
        case 1: W = w2; O = o2; K = 128; break;
        case 2: W = l2; O = o3; K = 128; break;
        case 3: W = l;  O = o4; K = 128; break;
        default: W = l1; O = o5; K = 128; break;
    }
    int idx = blockIdx.x * 256 + threadIdx.x;
    if (idx >= 6 * 8192) return;
    int blk = idx >> 13;
    int r = idx & 8191;
    int ch = r >> 11;
    int r2 = r & 2047;
    int pair = r2 >> 8;
    int ks = (r2 >> 7) & 1;
    int lane = (r2 >> 2) & 31;
    int w = r2 & 3;
    int g0 = lane >> 2, t = lane & 3;
    int jpar = w >> 1, wb = w & 1;
    int k = ch * 32 + ks * 16 + wb * 8 + t * 2;
    int n = pair * 16 + jpar * 8 + g0;
    const float* Wb = W + (size_t)blk * K * 128;
    float v0 = (k < K) ? Wb[(size_t)k * 128 + n] : 0.f;
    float v1 = (k + 1 < K) ? Wb[(size_t)(k + 1) * 128 + n] : 0.f;
    O[idx] = h2(v0, v1);
}

// ---------------- A loaders ----------------
__device__ __forceinline__ void loadA_g(float4* r, const float* __restrict__ A,
                                        int mBase, int k0, int M, int K, int tid) {
#pragma unroll
    for (int i = 0; i < 2; i++) {
        int q = tid + (i << 9);
        int row = q >> 3, kq = (q & 7) << 2;
        int gm = mBase + row, gk = k0 + kq;
        r[i] = make_float4(0.f, 0.f, 0.f, 0.f);
        if (gm < M && gk < K)
            r[i] = *reinterpret_cast<const float4*>(A + (size_t)gm * K + gk);
    }
}
__device__ __forceinline__ void storeA_f(uint32_t* __restrict__ buf, const float4* r, int tid) {
#pragma unroll
    for (int i4 = 0; i4 < 2; i4++) {
        int q = tid + (i4 << 9);
        int row = q >> 3, kq = (q & 7) << 2;
        int iT = row >> 4, rl = row & 15;
        int g = rl & 7, hr = rl >> 3;
        int ks = kq >> 4, kl = kq & 15;
        int w = hr + ((kl & 8) ? 2 : 0);
        int t0 = (kl & 7) >> 1;
        uint32_t* p = buf + iT * AI_STR + ks * KS_STR + (g * 4 + t0) * 4 + w;
        p[0] = h2(r[i4].x, r[i4].y);
        p[4] = h2(r[i4].z, r[i4].w);
    }
}

// ---------------- fragment loads ----------------
// B fragments for one chunk: bv[ks*2+p]
__device__ __forceinline__ void loadB_frag(uint4* bv, const uint32_t* __restrict__ Bg,
                                           int ch, int wid, int lane) {
    const uint32_t* Bb = Bg + ch * 2048 + ((wid >> 2) * 2) * 256 + lane * 4;
#pragma unroll
    for (int ks = 0; ks < 2; ks++)
#pragma unroll
        for (int p = 0; p < 2; p++)
            bv[ks * 2 + p] = *reinterpret_cast<const uint4*>(Bb + p * 256 + ks * 128);
}
// A fragments (edge, gmem) for one chunk: av[ks*2+i]
__device__ __forceinline__ void loadAe_frag(uint4* av, const uint32_t* __restrict__ Af, int ch) {
#pragma unroll
    for (int s = 0; s < 2; s++)
#pragma unroll
        for (int i = 0; i < 2; i++)
            av[s * 2 + i] = *reinterpret_cast<const uint4*>(Af + i * 1024 + (ch * 2 + s) * 128);
}

// ---------------- mma ----------------
__device__ __forceinline__ void mma8(float c[4][4], const uint4 av, const uint4* bv) {
#pragma unroll
    for (int j = 0; j < 4; j++) {
        uint32_t b0 = (j & 1) ? bv[j >> 1].z : bv[j >> 1].x;
        uint32_t b1 = (j & 1) ? bv[j >> 1].w : bv[j >> 1].y;
        asm volatile(
            "mma.sync.aligned.m16n8k16.row.col.f32.f16.f16.f32 "
            "{%0,%1,%2,%3}, {%4,%5,%6,%7}, {%8,%9}, {%0,%1,%2,%3};\n"
            : "+f"(c[j][0]), "+f"(c[j][1]), "+f"(c[j][2]), "+f"(c[j][3])
            : "r"(av.x), "r"(av.y), "r"(av.z), "r"(av.w), "r"(b0), "r"(b1));
    }
}
__device__ __forceinline__ void mma_bv(float c[2][4][4], const uint4* aC, const uint4* bv) {
#pragma unroll
    for (int ks = 0; ks < 2; ks++)
#pragma unroll
        for (int i = 0; i < 2; i++)
            mma8(c[i], aC[ks * 2 + i], &bv[ks * 2]);
}
// A from smem (stride ISTR), B preloaded
template<int ISTR>
__device__ __forceinline__ void mma_s_bv(const uint32_t* __restrict__ As, const uint4* bv,
                                         float c[2][4][4], int wid, int lane)
{
    const uint32_t* Ab = As + ((wid & 3) * 2) * ISTR + lane * 4;
#pragma unroll
    for (int ks = 0; ks < 2; ks++) {
        uint4 av[2];
#pragma unroll
        for (int i = 0; i < 2; i++)
            av[i] = *reinterpret_cast<const uint4*>(Ab + i * ISTR + ks * KS_STR);
#pragma unroll
        for (int i = 0; i < 2; i++)
            mma8(c[i], av[i], &bv[ks * 2]);
    }
}

__device__ __forceinline__ void zero_c(float c[2][4][4]) {
#pragma unroll
    for (int i = 0; i < 2; i++)
#pragma unroll
        for (int j = 0; j < 4; j++)
#pragma unroll
            for (int v = 0; v < 4; v++) c[i][j][v] = 0.0f;
}

__device__ __forceinline__ void store_T_frag(uint32_t* __restrict__ Tt, const float c[2][4][4],
                                             const float* bn, int wid, int g, int t,
                                             int warpN, bool doSsp)
{
    const int iTb = (wid & 3) * 2;
    const int ksBase = warpN >> 4;
#pragma unroll
    for (int i = 0; i < 2; i++)
#pragma unroll
        for (int half = 0; half < 2; half++)
#pragma unroll
            for (int j = 0; j < 4; j++) {
                float v0 = c[i][j][half * 2 + 0] + bn[j * 2 + 0];
                float v1 = c[i][j][half * 2 + 1] + bn[j * 2 + 1];
                if (doSsp) { v0 = sspf(v0); v1 = sspf(v1); }
                int ks = ksBase + (j >> 1);
                int w = half + 2 * (j & 1);
                Tt[(iTb + i) * TI_STR + ks * KS_STR + (g * 4 + t) * 4 + w] = h2(v0, v1);
            }
}

// ---------------- eattr pre-pack (tile-staged, coalesced; proven R9) --------------
__global__ void __launch_bounds__(256) pack_eattr(const float* __restrict__ ea,
                                                  uint32_t* __restrict__ out) {
    __shared__ uint32_t sf[8192];
    const int tile = blockIdx.x;
    const int tid = threadIdx.x;
    const int row = tid >> 1;
    const int kh = tid & 1;
    const float* er = ea + ((size_t)tile * 128 + row) * EC;
    const int iT = row >> 4, rl = row & 15;
    const int g = rl & 7, hr = rl >> 3;
#pragma unroll
    for (int q = 0; q < 4; q++) {
#pragma unroll
        for (int f4 = 0; f4 < 4; f4++) {
            int kq = kh * 64 + (q * 4 + f4) * 4;
            float4 v = make_float4(0.f, 0.f, 0.f, 0.f);
            if (kq < EC) {
                if (kq + 3 < EC)
                    v = *reinterpret_cast<const float4*>(er + kq);
                else {
                    v.x = er[kq];
                    if (kq + 1 < EC) v.y = er[kq + 1];
                    if (kq + 2 < EC) v.z = er[kq + 2];
                }
            }
            int ks = kq >> 4, kl = kq & 15;
            int w = hr + ((kl & 8) ? 2 : 0);
            int t0 = (kl & 7) >> 1;
            uint32_t* p = sf + iT * 1024 + ks * 128 + (g * 4 + t0) * 4 + w;
            p[0] = h2(v.x, v.y);
            p[4] = h2(v.z, v.w);
        }
    }
    __syncthreads();
    uint32_t* o = out + (size_t)tile * 8192;
#pragma unroll
    for (int i = 0; i < 8; i++)
        *reinterpret_cast<uint4*>(o + (tid + i * 256) * 4) =
            *reinterpret_cast<const uint4*>(sf + (tid + i * 256) * 4);
}

// ---------------- fused edge kernel ----------------
__global__ void __launch_bounds__(NT, 1) edge_fused(
    const uint32_t* __restrict__ eaf,
    const uint32_t* __restrict__ B1g, const float* __restrict__ b1,
    const uint32_t* __restrict__ B2g, const float* __restrict__ b2,
    const float* __restrict__ Cm, const int* __restrict__ src, const int* __restrict__ dst,
    const float* __restrict__ x, float* __restrict__ agg)
{
    extern __shared__ uint32_t sm[];
    uint32_t* Tt = sm;

    const int tid = threadIdx.x;
    const int wid = tid >> 5, lane = tid & 31;
    const int g = lane >> 2, t = lane & 3;
    const int warpM = (wid & 3) * 32, warpN = (wid >> 2) * 32;
    const int mBase = blockIdx.x * 128;

    float c[2][4][4];
    zero_c(c);

    // stage 1: all-register, fully pipelined (A and B prefetch)
    const uint32_t* Af = eaf + (size_t)blockIdx.x * 8192 + ((wid & 3) * 2) * 1024 + lane * 4;
    uint4 aC[4], bv[4], aN[4], bN[4];
    loadAe_frag(aC, Af, 0);
    loadB_frag(bv, B1g, 0, wid, lane);
#pragma unroll
    for (int ch = 0; ch < 4; ch++) {
        if (ch < 3) {
            loadAe_frag(aN, Af, ch + 1);
            loadB_frag(bN, B1g, ch + 1, wid, lane);
        }
        mma_bv(c, aC, bv);
        if (ch < 3) {
#pragma unroll
            for (int q = 0; q < 4; q++) { aC[q] = aN[q]; bv[q] = bN[q]; }
        }
    }

    float bn1[8];
#pragma unroll
    for (int j = 0; j < 4; j++) {
        bn1[j * 2 + 0] = __ldg(b1 + warpN + j * 8 + t * 2 + 0);
        bn1[j * 2 + 1] = __ldg(b1 + warpN + j * 8 + t * 2 + 1);
    }
    store_T_frag(Tt, c, bn1, wid, g, t, warpN, true);
    zero_c(c);

    // prefetch epilogue metadata (hidden under stage 2)
    float cmv4[4]; int s4[4], d4[4];
#pragma unroll
    for (int i = 0; i < 2; i++)
#pragma unroll
        for (int half = 0; half < 2; half++) {
            const int e = mBase + warpM + i * 16 + g + half * 8;
            cmv4[i * 2 + half] = __ldg(Cm + e);
            s4[i * 2 + half] = __ldg(src + e);
            d4[i * 2 + half] = __ldg(dst + e);
        }

    loadB_frag(bv, B2g, 0, wid, lane);
    __syncthreads();   // T visible to all warps

    // stage 2: T (smem) @ B2, B pipelined
#pragma unroll
    for (int ch = 0; ch < 4; ch++) {
        if (ch < 3) loadB_frag(bN, B2g, ch + 1, wid, lane);
        mma_s_bv<TI_STR>(Tt + ch * 2 * KS_STR, bv, c, wid, lane);
        if (ch < 3) {
#pragma unroll
            for (int q = 0; q < 4; q++) bv[q] = bN[q];
        }
    }

    // scatter epilogue: guarded red.global.add.v2.f32
    float bn2[8];
#pragma unroll
    for (int j = 0; j < 4; j++) {
        bn2[j * 2 + 0] = __ldg(b2 + warpN + j * 8 + t * 2 + 0);
        bn2[j * 2 + 1] = __ldg(b2 + warpN + j * 8 + t * 2 + 1);
    }
#pragma unroll
    for (int i = 0; i < 2; i++)
#pragma unroll
        for (int half = 0; half < 2; half++) {
            const float cmv = cmv4[i * 2 + half];
            if (cmv != 0.0f) {
                const float* xr = x + (size_t)s4[i * 2 + half] * 128;
                float* ar = agg + (size_t)d4[i * 2 + half] * 128;
#pragma unroll
                for (int j = 0; j < 4; j++) {
                    const int col = warpN + j * 8 + t * 2;
                    float2 xv = *reinterpret_cast<const float2*>(xr + col);
                    float w0 = (c[i][j][half * 2 + 0] + bn2[j * 2 + 0]) * cmv;
                    float w1 = (c[i][j][half * 2 + 1] + bn2[j * 2 + 1]) * cmv;
                    float m0 = xv.x * w0, m1 = xv.y * w1;
                    asm volatile("red.global.add.v2.f32 [%0], {%1, %2};"
                                 :: "l"(ar + col), "f"(m0), "f"(m1) : "memory");
                }
            }
        }
}

// ---------------- fused node kernel ----------------
__global__ void __launch_bounds__(NT, 1) node_fused(
    const float* __restrict__ agg,
    const uint32_t* __restrict__ B1g, const float* __restrict__ b1,
    const uint32_t* __restrict__ B2g, const float* __restrict__ b2,
    float* __restrict__ h, const uint32_t* __restrict__ B3g, float* __restrict__ xOut)
{
    extern __shared__ uint32_t sm[];
    uint32_t* Tt  = sm;
    uint32_t* As0 = sm + TWORDS;
    uint32_t* As1 = As0 + AWORDS;

    const int tid = threadIdx.x;
    const int wid = tid >> 5, lane = tid & 31;
    const int g = lane >> 2, t = lane & 3;
    const int warpM = (wid & 3) * 32, warpN = (wid >> 2) * 32;
    const int mBase = blockIdx.x * 128;

    float c[2][4][4];
    zero_c(c);
    float4 aR[2];
    uint4 bv[4], bN[4];

    // stage 1: agg (smem-staged A, double-buffered) @ B1 (B pipelined)
    loadA_g(aR, agg, mBase, 0, N_NODES, 128, tid);
    loadB_frag(bv, B1g, 0, wid, lane);
    storeA_f(As0, aR, tid);
    __syncthreads();
#pragma unroll
    for (int ch = 0; ch < 4; ch++) {
        if (ch < 3) {
            loadA_g(aR, agg, mBase, (ch + 1) * 32, N_NODES, 128, tid);
            loadB_frag(bN, B1g, ch + 1, wid, lane);
        }
        mma_s_bv<AI_STR>((ch & 1) ? As1 : As0, bv, c, wid, lane);
        if (ch < 3) {
            storeA_f(((ch + 1) & 1) ? As1 : As0, aR, tid);
#pragma unroll
            for (int q = 0; q < 4; q++) bv[q] = bN[q];
        }
        __syncthreads();
    }

    float bn1[8];
#pragma unroll
    for (int j = 0; j < 4; j++) {
        bn1[j * 2 + 0] = __ldg(b1 + warpN + j * 8 + t * 2 + 0);
        bn1[j * 2 + 1] = __ldg(b1 + warpN + j * 8 + t * 2 + 1);
    }
    store_T_frag(Tt, c, bn1, wid, g, t, warpN, true);
    zero_c(c);
    loadB_frag(bv, B2g, 0, wid, lane);
    __syncthreads();

    // stage 2: T @ B2 (B pipelined)
#pragma unroll
    for (int ch = 0; ch < 4; ch++) {
        if (ch < 3) loadB_frag(bN, B2g, ch + 1, wid, lane);
        mma_s_bv<TI_STR>(Tt + ch * 2 * KS_STR, bv, c, wid, lane);
        if (ch < 3) {
#pragma unroll
            for (int q = 0; q < 4; q++) bv[q] = bN[q];
        }
    }
    __syncthreads();   // all warps done reading Tt before epilogue overwrites it

    // stage-2 epilogue: h += residual; keep hnew resident in T-frag
    float bn2[8];
#pragma unroll
    for (int j = 0; j < 4; j++) {
        bn2[j * 2 + 0] = __ldg(b2 + warpN + j * 8 + t * 2 + 0);
        bn2[j * 2 + 1] = __ldg(b2 + warpN + j * 8 + t * 2 + 1);
    }
    const int iTb = (wid & 3) * 2;
    const int ksBase = warpN >> 4;
#pragma unroll
    for (int i = 0; i < 2; i++)
#pragma unroll
        for (int half = 0; half < 2; half++) {
            const int gm = mBase + warpM + i * 16 + g + half * 8;
            const bool ok = gm < N_NODES;
            float* hrow = h + (size_t)gm * 128;
#pragma unroll
            for (int j = 0; j < 4; j++) {
                const int col = warpN + j * 8 + t * 2;
                float v0 = c[i][j][half * 2 + 0] + bn2[j * 2 + 0];
                float v1 = c[i][j][half * 2 + 1] + bn2[j * 2 + 1];
                if (ok) {
                    float2 hv = *reinterpret_cast<const float2*>(hrow + col);
                    v0 += hv.x; v1 += hv.y;
                    *reinterpret_cast<float2*>(hrow + col) = make_float2(v0, v1);
                }
                int ks = ksBase + (j >> 1);
                int w = half + 2 * (j & 1);
                Tt[(iTb + i) * TI_STR + ks * KS_STR + (g * 4 + t) * 4 + w] = h2(v0, v1);
            }
        }

    // stage 3: xOut = hnew @ lin1next (B pipelined)
    if (B3g != nullptr) {
        zero_c(c);
        loadB_frag(bv, B3g, 0, wid, lane);
        __syncthreads();   // hnew T-frag complete
#pragma unroll
        for (int ch = 0; ch < 4; ch++) {
            if (ch < 3) loadB_frag(bN, B3g, ch + 1, wid, lane);
            mma_s_bv<TI_STR>(Tt + ch * 2 * KS_STR, bv, c, wid, lane);
            if (ch < 3) {
#pragma unroll
                for (int q = 0; q < 4; q++) bv[q] = bN[q];
            }
        }
#pragma unroll
        for (int i = 0; i < 2; i++)
#pragma unroll
            for (int half = 0; half < 2; half++) {
                const int gm = mBase + warpM + i * 16 + g + half * 8;
                if (gm < N_NODES) {
                    float* orow = xOut + (size_t)gm * 128;
#pragma unroll
                    for (int j = 0; j < 4; j++) {
                        const int col = warpN + j * 8 + t * 2;
                        *reinterpret_cast<float2*>(orow + col) =
                            make_float2(c[i][j][half * 2 + 0], c[i][j][half * 2 + 1]);
                    }
                }
            }
    }
}

// ---------------- plain GEMM (initial x = h @ lin1_0) ----------------
__global__ void __launch_bounds__(NT, 1) gemm_plain(
    const float* __restrict__ A, const uint32_t* __restrict__ Bg,
    float* __restrict__ out, int M)
{
    extern __shared__ uint32_t sm[];
    uint32_t* As0 = sm;
    uint32_t* As1 = As0 + AWORDS;

    const int tid = threadIdx.x;
    const int wid = tid >> 5, lane = tid & 31;
    const int g = lane >> 2, t = lane & 3;
    const int warpM = (wid & 3) * 32, warpN = (wid >> 2) * 32;
    const int mBase = blockIdx.x * 128;

    float c[2][4][4];
    zero_c(c);
    float4 aR[2];
    uint4 bv[4], bN[4];
    loadA_g(aR, A, mBase, 0, M, 128, tid);
    loadB_frag(bv, Bg, 0, wid, lane);
    storeA_f(As0, aR, tid);
    __syncthreads();
#pragma unroll
    for (int ch = 0; ch < 4; ch++) {
        if (ch < 3) {
            loadA_g(aR, A, mBase, (ch + 1) * 32, M, 128, tid);
            loadB_frag(bN, Bg, ch + 1, wid, lane);
        }
        mma_s_bv<AI_STR>((ch & 1) ? As1 : As0, bv, c, wid, lane);
        if (ch < 3) {
            storeA_f(((ch + 1) & 1) ? As1 : As0, aR, tid);
#pragma unroll
            for (int q = 0; q < 4; q++) bv[q] = bN[q];
        }
        __syncthreads();
    }
#pragma unroll
    for (int i = 0; i < 2; i++)
#pragma unroll
        for (int half = 0; half < 2; half++) {
            const int gm = mBase + warpM + i * 16 + g + half * 8;
            if (gm < M) {
                float* orow = out + (size_t)gm * 128;
#pragma unroll
                for (int j = 0; j < 4; j++) {
                    const int col = warpN + j * 8 + t * 2;
                    *reinterpret_cast<float2*>(orow + col) =
                        make_float2(c[i][j][half * 2 + 0], c[i][j][half * 2 + 1]);
                }
            }
        }
}

// ---------------- small kernels ----------------
__global__ void embed_kernel(const float* __restrict__ z, const float* __restrict__ w,
                             const float* __restrict__ b, float* __restrict__ h) {
    int n = blockIdx.x, j = threadIdx.x;
    const float* zr = z + (size_t)n * (IN_DIM + HID);
    float acc = b[j] + zr[IN_DIM + j];
#pragma unroll
    for (int k = 0; k < IN_DIM; k++) acc = fmaf(zr[k], w[k * HID + j], acc);
    h[(size_t)n * HID + j] = acc;
}

__global__ void cmask_kernel(const float* __restrict__ len, float* __restrict__ C) {
    int e = blockIdx.x * 256 + threadIdx.x;
    if (e < N_EDGES) {
        float l = len[e];
        C[e] = (l <= 10.0f && l >= 0.0f) ? 1.0f : 0.0f;
    }
}

__global__ void zero_kernel(float4* __restrict__ p, int n4) {
    int i = blockIdx.x * 256 + threadIdx.x;
    if (i < n4) p[i] = make_float4(0.f, 0.f, 0.f, 0.f);
}

// ---------------- host launch ----------------
extern "C" void kernel_launch(void* const* d_in, const int* in_sizes, int n_in,
                              void* d_out, int out_size) {
    const float* z      = (const float*)d_in[0];
    const int*   ei     = (const int*)  d_in[1];
    const float* elen   = (const float*)d_in[2];
    const float* eattr  = (const float*)d_in[3];
    const float* emb_w  = (const float*)d_in[4];
    const float* emb_b  = (const float*)d_in[5];
    const float* lin1_w = (const float*)d_in[6];
    const float* nn_w1  = (const float*)d_in[7];
    const float* nn_b1  = (const float*)d_in[8];
    const float* nn_w2  = (const float*)d_in[9];
    const float* nn_b2  = (const float*)d_in[10];
    const float* lin2_w = (const float*)d_in[11];
    const float* lin2_b = (const float*)d_in[12];
    const float* lin_w  = (const float*)d_in[13];
    const float* lin_b  = (const float*)d_in[14];
    float* h = (float*)d_out;

    float *px, *pagg, *pC;
    uint32_t *peaf, *pw1, *pw2, *pl2, *pl, *pl1;
    cudaGetSymbolAddress((void**)&px,   g_x);
    cudaGetSymbolAddress((void**)&pagg, g_agg);
    cudaGetSymbolAddress((void**)&pC,   g_C);
    cudaGetSymbolAddress((void**)&peaf, g_eaf);
    cudaGetSymbolAddress((void**)&pw1,  g_w1f);
    cudaGetSymbolAddress((void**)&pw2,  g_w2f);
    cudaGetSymbolAddress((void**)&pl2,  g_l2f);
    cudaGetSymbolAddress((void**)&pl,   g_lf);
    cudaGetSymbolAddress((void**)&pl1,  g_l1f);

    cudaFuncSetAttribute(edge_fused, cudaFuncAttributeMaxDynamicSharedMemorySize, EDGE_SMEM);
    cudaFuncSetAttribute(node_fused, cudaFuncAttributeMaxDynamicSharedMemorySize, NODE_SMEM);
    cudaFuncSetAttribute(gemm_plain, cudaFuncAttributeMaxDynamicSharedMemorySize, PLAIN_SMEM);

    const int* src = ei;
    const int* dst = ei + N_EDGES;

    embed_kernel<<<N_NODES, HID>>>(z, emb_w, emb_b, h);
    cmask_kernel<<<(N_EDGES + 255) / 256, 256>>>(elen, pC);
    pack_eattr<<<NTILES, 256>>>(eattr, peaf);
    {
        dim3 gw((6 * 8192 + 255) / 256, 5);
        pack_w<<<gw, 256>>>(nn_w1, nn_w2, lin2_w, lin_w, lin1_w, pw1, pw2, pl2, pl, pl1);
    }

    const int nodeTiles = (N_NODES + 127) / 128;   // 391
    const int aggN4 = N_NODES * HID / 4;

    gemm_plain<<<nodeTiles, NT, PLAIN_SMEM>>>(h, pl1, px, N_NODES);

    for (int i = 0; i < N_BLOCKS; i++) {
        zero_kernel<<<(aggN4 + 255) / 256, 256>>>((float4*)pagg, aggN4);
        edge_fused<<<NTILES, NT, EDGE_SMEM>>>(
            peaf, pw1 + i * 8192, nn_b1 + (size_t)i * HID,
            pw2 + i * 8192, nn_b2 + (size_t)i * HID,
            pC, src, dst, px, pagg);
        const uint32_t* lin1next = (i + 1 < N_BLOCKS) ? (pl1 + (i + 1) * 8192) : nullptr;
        node_fused<<<nodeTiles, NT, NODE_SMEM>>>(
            pagg, pl2 + i * 8192, lin2_b + (size_t)i * HID,
            pl + i * 8192, lin_b + (size_t)i * HID,
            h, lin1next, px);
    }
}